// round 2
// baseline (speedup 1.0000x reference)
#include <cuda_runtime.h>
#include <math.h>

// ---------------- problem constants ----------------
#define BB   16      // batch
#define LK   64      // source length
#define LQ   64      // query length
#define DD   300     // embedding dim
#define HH   512     // encoder hidden
#define H2   1024    // 2*H (decoder hidden / enc_out channels)
#define HG   2048    // 4*H  encoder gates
#define DG   4096    // 8*H  decoder gates
#define VV   10000   // vocab

// ---------------- scratch (device globals; no allocation) ----------------
__device__ float g_xs_src[BB * LK * DD];
__device__ float g_xs_prev[BB * LQ * DD];
__device__ float g_xg_f[BB * LK * HG];
__device__ float g_xg_b[BB * LK * HG];
__device__ float g_xg_d[BB * LQ * DG];
__device__ float g_WT_f[HH * HG];     // [k<512][n<2048]
__device__ float g_WT_b[HH * HG];
__device__ float g_WT_d[H2 * DG];     // [k<1024][n<4096]
__device__ float g_he[2 * BB * HH];   // enc h (dir, b, j)
__device__ float g_ce[2 * BB * HH];
__device__ float g_pre_e[2 * BB * HG];
__device__ float g_hd[BB * H2];
__device__ float g_cd[BB * H2];
__device__ float g_pre_d[BB * DG];
__device__ float g_enc[BB * LK * H2];
__device__ float g_Kb[BB * LK * H2];
__device__ float g_Vb[BB * LK * H2];
__device__ float g_att[BB * LQ * LK];
__device__ float g_cat[BB * LQ * 2 * H2];
__device__ float g_x1[BB * LQ * H2];

__device__ __forceinline__ float sigf(float x) { return 1.f / (1.f + expf(-x)); }

// ---------------- small utility kernels ----------------
__global__ void k_zero_enc_states() {
    int i = blockIdx.x * blockDim.x + threadIdx.x;
    int n = 2 * BB * HH;
    if (i < n) { g_he[i] = 0.f; g_ce[i] = 0.f; }
}

__global__ void k_embed(const int* __restrict__ idx, const float* __restrict__ emb,
                        float* __restrict__ out, int rows) {
    int i = blockIdx.x * blockDim.x + threadIdx.x;
    if (i < rows * DD) {
        int r = i / DD, d = i - r * DD;
        out[i] = emb[(long)idx[r] * DD + d];
    }
}

// in[R][C] -> out[C][R]
__global__ void k_transpose(const float* __restrict__ in, float* __restrict__ out,
                            int R, int C) {
    __shared__ float tile[32][33];
    int c0 = blockIdx.x * 32, r0 = blockIdx.y * 32;
    int c = c0 + threadIdx.x;
    #pragma unroll
    for (int i = 0; i < 32; i += 8) {
        int r = r0 + threadIdx.y + i;
        if (r < R && c < C) tile[threadIdx.y + i][threadIdx.x] = in[(long)r * C + c];
    }
    __syncthreads();
    int oc = r0 + threadIdx.x;
    #pragma unroll
    for (int i = 0; i < 32; i += 8) {
        int orr = c0 + threadIdx.y + i;
        if (orr < C && oc < R) out[(long)orr * R + oc] = tile[threadIdx.x][threadIdx.y + i];
    }
}

// ---------------- generic tiled GEMM: C[M,N] = A[M,K] @ W[N,K]^T (+bias)(+tanh) ----------------
// batched via grid.z with element strides sA,sW,sC. block (16,16), 64x64 tile, 4x4 microtile.
__global__ void k_gemm(const float* __restrict__ A, const float* __restrict__ W,
                       const float* __restrict__ bias, float* __restrict__ C,
                       int M, int N, int K, long sA, long sW, long sC, int act) {
    A += (long)blockIdx.z * sA;
    W += (long)blockIdx.z * sW;
    C += (long)blockIdx.z * sC;
    __shared__ float As[16][68];
    __shared__ float Ws[16][68];
    int m0 = blockIdx.y * 64, n0 = blockIdx.x * 64;
    int tx = threadIdx.x, ty = threadIdx.y;
    int tid = ty * 16 + tx;
    float acc[4][4] = {};
    for (int kk = 0; kk < K; kk += 16) {
        #pragma unroll
        for (int s = 0; s < 4; s++) {
            int e = tid + s * 256;
            int mm = e >> 4, k = e & 15;
            float va = 0.f, vw = 0.f;
            if (m0 + mm < M && kk + k < K) va = A[(long)(m0 + mm) * K + kk + k];
            if (n0 + mm < N && kk + k < K) vw = W[(long)(n0 + mm) * K + kk + k];
            As[k][mm] = va;
            Ws[k][mm] = vw;
        }
        __syncthreads();
        #pragma unroll
        for (int k = 0; k < 16; k++) {
            float a[4], w[4];
            #pragma unroll
            for (int i = 0; i < 4; i++) a[i] = As[k][ty * 4 + i];
            #pragma unroll
            for (int j = 0; j < 4; j++) w[j] = Ws[k][tx * 4 + j];
            #pragma unroll
            for (int i = 0; i < 4; i++)
                #pragma unroll
                for (int j = 0; j < 4; j++) acc[i][j] += a[i] * w[j];
        }
        __syncthreads();
    }
    #pragma unroll
    for (int i = 0; i < 4; i++) {
        int m = m0 + ty * 4 + i;
        if (m >= M) continue;
        #pragma unroll
        for (int j = 0; j < 4; j++) {
            int n = n0 + tx * 4 + j;
            if (n >= N) continue;
            float v = acc[i][j];
            if (bias) v += bias[n];
            if (act == 1) v = tanhf(v);
            C[(long)m * N + n] = v;
        }
    }
}

// ---------------- encoder LSTM step ----------------
// grid: (HG/128, BB/4, 2 dirs), block 128. pre[dir,b,n] = xg[b,t_eff,n] + h[b,:]·WT[:,n]
__global__ void k_enc_matvec(int t) {
    int dir = blockIdx.z;
    int b0 = blockIdx.y * 4;
    int n = blockIdx.x * 128 + threadIdx.x;
    const float* WT = dir ? g_WT_b : g_WT_f;
    const float* hsrc = g_he + dir * BB * HH;
    __shared__ float hs[4][HH];
    for (int i = threadIdx.x; i < 4 * HH; i += 128) {
        int bb = i / HH, k = i - bb * HH;
        hs[bb][k] = hsrc[(b0 + bb) * HH + k];
    }
    __syncthreads();
    float acc0 = 0.f, acc1 = 0.f, acc2 = 0.f, acc3 = 0.f;
    #pragma unroll 4
    for (int k = 0; k < HH; k++) {
        float w = WT[(long)k * HG + n];
        acc0 += hs[0][k] * w;
        acc1 += hs[1][k] * w;
        acc2 += hs[2][k] * w;
        acc3 += hs[3][k] * w;
    }
    int tt = dir ? (LK - 1 - t) : t;
    const float* xg = dir ? g_xg_b : g_xg_f;
    float* pre = g_pre_e + (long)dir * BB * HG;
    pre[(long)(b0 + 0) * HG + n] = xg[((long)(b0 + 0) * LK + tt) * HG + n] + acc0;
    pre[(long)(b0 + 1) * HG + n] = xg[((long)(b0 + 1) * LK + tt) * HG + n] + acc1;
    pre[(long)(b0 + 2) * HG + n] = xg[((long)(b0 + 2) * LK + tt) * HG + n] + acc2;
    pre[(long)(b0 + 3) * HG + n] = xg[((long)(b0 + 3) * LK + tt) * HG + n] + acc3;
}

__global__ void k_enc_cell(int t) {
    int idx = blockIdx.x * blockDim.x + threadIdx.x;
    if (idx >= 2 * BB * HH) return;
    int dir = idx / (BB * HH);
    int r = idx - dir * BB * HH;
    int b = r / HH, j = r - b * HH;
    const float* pre = g_pre_e + (long)dir * BB * HG + (long)b * HG;
    float i_ = pre[j], f_ = pre[HH + j], gg = pre[2 * HH + j], o_ = pre[3 * HH + j];
    int si = dir * BB * HH + b * HH + j;
    float c = sigf(f_) * g_ce[si] + sigf(i_) * tanhf(gg);
    float h = sigf(o_) * tanhf(c);
    g_ce[si] = c;
    g_he[si] = h;
    int tt = dir ? (LK - 1 - t) : t;
    g_enc[((long)b * LK + tt) * H2 + dir * HH + j] = h;
}

// ---------------- decoder init: interleave fwd/bwd final states ----------------
__global__ void k_dec_init() {
    int idx = blockIdx.x * blockDim.x + threadIdx.x;
    if (idx >= BB * H2) return;
    int b = idx / H2, jj = idx - b * H2;
    int dir = jj & 1, j = jj >> 1;
    g_hd[idx] = g_he[dir * BB * HH + b * HH + j];
    g_cd[idx] = g_ce[dir * BB * HH + b * HH + j];
}

// ---------------- decoder LSTM step ----------------
__global__ void k_dec_matvec(int t) {
    int b0 = blockIdx.y * 4;
    int n = blockIdx.x * 128 + threadIdx.x;
    __shared__ float hs[4][H2];
    for (int i = threadIdx.x; i < 4 * H2; i += 128) {
        int bb = i / H2, k = i - bb * H2;
        hs[bb][k] = g_hd[(b0 + bb) * H2 + k];
    }
    __syncthreads();
    float acc0 = 0.f, acc1 = 0.f, acc2 = 0.f, acc3 = 0.f;
    #pragma unroll 4
    for (int k = 0; k < H2; k++) {
        float w = g_WT_d[(long)k * DG + n];
        acc0 += hs[0][k] * w;
        acc1 += hs[1][k] * w;
        acc2 += hs[2][k] * w;
        acc3 += hs[3][k] * w;
    }
    g_pre_d[(long)(b0 + 0) * DG + n] = g_xg_d[((long)(b0 + 0) * LQ + t) * DG + n] + acc0;
    g_pre_d[(long)(b0 + 1) * DG + n] = g_xg_d[((long)(b0 + 1) * LQ + t) * DG + n] + acc1;
    g_pre_d[(long)(b0 + 2) * DG + n] = g_xg_d[((long)(b0 + 2) * LQ + t) * DG + n] + acc2;
    g_pre_d[(long)(b0 + 3) * DG + n] = g_xg_d[((long)(b0 + 3) * LQ + t) * DG + n] + acc3;
}

__global__ void k_dec_cell(int t) {
    int idx = blockIdx.x * blockDim.x + threadIdx.x;
    if (idx >= BB * H2) return;
    int b = idx / H2, j = idx - b * H2;
    const float* pre = g_pre_d + (long)b * DG;
    float i_ = pre[j], f_ = pre[H2 + j], gg = pre[2 * H2 + j], o_ = pre[3 * H2 + j];
    float c = sigf(f_) * g_cd[idx] + sigf(i_) * tanhf(gg);
    float h = sigf(o_) * tanhf(c);
    g_cd[idx] = c;
    g_hd[idx] = h;
    // decoder output h_t goes to Q and to second half of fc1 concat input
    long base = ((long)b * LQ + t);
    // Q buffer for attention
    g_x1[0] = g_x1[0]; // no-op to keep compiler honest (removed by opt)
    ((float*)g_cat)[base * (2 * H2) + H2 + j] = h;
    // store into Q
    extern __device__ float g_Q_alias[];
    (void)g_Q_alias;
    g_att[0] = g_att[0]; // placeholder no-op
    // actual Q write:
    g_Kb[0] = g_Kb[0];
    // (see below: Q stored in dedicated buffer)
    g_Vb[0] = g_Vb[0];
    // real write:
    g_x1[base * H2 + j] = h; // TEMP: reuse g_x1 as Q storage until fc1 (fc1 overwrites later)
}

// ---------------- softmax over k with PAD mask ----------------
__global__ void k_softmax(const int* __restrict__ source) {
    int b = blockIdx.y, q = blockIdx.x;
    int k = threadIdx.x; // 64
    long off = ((long)b * LQ + q) * LK;
    float s = g_att[off + k];
    if (source[b * LK + k] == 0) s = -INFINITY;
    __shared__ float red[64];
    red[k] = s;
    __syncthreads();
    #pragma unroll
    for (int st = 32; st > 0; st >>= 1) {
        if (k < st) red[k] = fmaxf(red[k], red[k + st]);
        __syncthreads();
    }
    float mx = red[0];
    __syncthreads();
    float e = expf(s - mx);
    red[k] = e;
    __syncthreads();
    #pragma unroll
    for (int st = 32; st > 0; st >>= 1) {
        if (k < st) red[k] += red[k + st];
        __syncthreads();
    }
    g_att[off + k] = e / red[0];
}

// ---------------- ctx = A @ V, written into first half of concat buffer ----------------
// grid (H2/128, LQ/16, BB), block 128
__global__ void k_ctx() {
    int b = blockIdx.z;
    int q0 = blockIdx.y * 16;
    int c = blockIdx.x * 128 + threadIdx.x;
    __shared__ float As[16][64];
    for (int i = threadIdx.x; i < 16 * 64; i += 128)
        As[i / 64][i & 63] = g_att[((long)b * LQ + q0 + i / 64) * LK + (i & 63)];
    __syncthreads();
    float acc[16] = {};
    for (int k = 0; k < LK; k++) {
        float v = g_Vb[((long)b * LK + k) * H2 + c];
        #pragma unroll
        for (int q = 0; q < 16; q++) acc[q] += As[q][k] * v;
    }
    #pragma unroll
    for (int q = 0; q < 16; q++)
        g_cat[((long)b * LQ + q0 + q) * (2 * H2) + c] = acc[q];
}

// copy Q (stored temporarily in g_x1) is not needed: scores GEMM reads g_x1 directly,
// and g_cat second half was written by k_dec_cell.

// ---------------- host launch ----------------
extern "C" void kernel_launch(void* const* d_in, const int* in_sizes, int n_in,
                              void* d_out, int out_size) {
    const int*   source   = (const int*)  d_in[0];
    const int*   prev     = (const int*)  d_in[1];
    const float* emb      = (const float*)d_in[2];
    const float* ef_Wih   = (const float*)d_in[3];
    const float* ef_Whh   = (const float*)d_in[4];
    const float* ef_b     = (const float*)d_in[5];
    const float* eb_Wih   = (const float*)d_in[6];
    const float* eb_Whh   = (const float*)d_in[7];
    const float* eb_b     = (const float*)d_in[8];
    const float* d_Wih    = (const float*)d_in[9];
    const float* d_Whh    = (const float*)d_in[10];
    const float* d_b      = (const float*)d_in[11];
    const float* k_W      = (const float*)d_in[12];
    const float* k_b      = (const float*)d_in[13];
    const float* v_W      = (const float*)d_in[14];
    const float* v_b      = (const float*)d_in[15];
    const float* fc1_W    = (const float*)d_in[16];
    const float* fc1_b    = (const float*)d_in[17];
    const float* fc2_W    = (const float*)d_in[18];
    const float* fc2_b    = (const float*)d_in[19];
    float* out = (float*)d_out;

    float *p_xs_src, *p_xs_prev, *p_xg_f, *p_xg_b, *p_xg_d;
    float *p_WT_f, *p_WT_b, *p_WT_d, *p_enc, *p_K, *p_V, *p_att, *p_cat, *p_x1;
    cudaGetSymbolAddress((void**)&p_xs_src, g_xs_src);
    cudaGetSymbolAddress((void**)&p_xs_prev, g_xs_prev);
    cudaGetSymbolAddress((void**)&p_xg_f, g_xg_f);
    cudaGetSymbolAddress((void**)&p_xg_b, g_xg_b);
    cudaGetSymbolAddress((void**)&p_xg_d, g_xg_d);
    cudaGetSymbolAddress((void**)&p_WT_f, g_WT_f);
    cudaGetSymbolAddress((void**)&p_WT_b, g_WT_b);
    cudaGetSymbolAddress((void**)&p_WT_d, g_WT_d);
    cudaGetSymbolAddress((void**)&p_enc, g_enc);
    cudaGetSymbolAddress((void**)&p_K, g_Kb);
    cudaGetSymbolAddress((void**)&p_V, g_Vb);
    cudaGetSymbolAddress((void**)&p_att, g_att);
    cudaGetSymbolAddress((void**)&p_cat, g_cat);
    cudaGetSymbolAddress((void**)&p_x1, g_x1);

    dim3 gblk(16, 16);

    // 0. zero encoder states
    k_zero_enc_states<<<(2 * BB * HH + 255) / 256, 256>>>();

    // 1. embeddings
    k_embed<<<(BB * LK * DD + 255) / 256, 256>>>(source, emb, p_xs_src, BB * LK);
    k_embed<<<(BB * LQ * DD + 255) / 256, 256>>>(prev, emb, p_xs_prev, BB * LQ);

    // 2. transpose recurrent weights: Whh[N=4G][K=G] -> WT[G][4G]
    k_transpose<<<dim3((HH + 31) / 32, (HG + 31) / 32), dim3(32, 8)>>>(ef_Whh, p_WT_f, HG, HH);
    k_transpose<<<dim3((HH + 31) / 32, (HG + 31) / 32), dim3(32, 8)>>>(eb_Whh, p_WT_b, HG, HH);
    k_transpose<<<dim3((H2 + 31) / 32, (DG + 31) / 32), dim3(32, 8)>>>(d_Whh, p_WT_d, DG, H2);

    // 3. input pregates xg = xs @ Wih^T + b
    k_gemm<<<dim3(HG / 64, (BB * LK) / 64, 1), gblk>>>(p_xs_src, ef_Wih, ef_b, p_xg_f,
        BB * LK, HG, DD, 0, 0, 0, 0);
    k_gemm<<<dim3(HG / 64, (BB * LK) / 64, 1), gblk>>>(p_xs_src, eb_Wih, eb_b, p_xg_b,
        BB * LK, HG, DD, 0, 0, 0, 0);
    k_gemm<<<dim3(DG / 64, (BB * LQ) / 64, 1), gblk>>>(p_xs_prev, d_Wih, d_b, p_xg_d,
        BB * LQ, DG, DD, 0, 0, 0, 0);

    // 4. encoder recurrence (fwd + bwd fused per step)
    for (int t = 0; t < LK; t++) {
        k_enc_matvec<<<dim3(HG / 128, BB / 4, 2), 128>>>(t);
        k_enc_cell<<<(2 * BB * HH + 255) / 256, 256>>>(t);
    }

    // 5. decoder init + recurrence
    k_dec_init<<<(BB * H2 + 255) / 256, 256>>>();
    for (int t = 0; t < LQ; t++) {
        k_dec_matvec<<<dim3(DG / 128, BB / 4, 1), 128>>>(t);
        k_dec_cell<<<(BB * H2 + 255) / 256, 256>>>(t);
    }

    // 6. K and V projections on enc_out
    k_gemm<<<dim3(H2 / 64, (BB * LK) / 64, 1), gblk>>>(p_enc, k_W, k_b, p_K,
        BB * LK, H2, H2, 0, 0, 0, 0);
    k_gemm<<<dim3(H2 / 64, (BB * LK) / 64, 1), gblk>>>(p_enc, v_W, v_b, p_V,
        BB * LK, H2, H2, 0, 0, 0, 0);

    // 7. scores M[b,q,k] = Q[b,q,:] · K[b,k,:]   (Q currently stored in g_x1)
    k_gemm<<<dim3(1, 1, BB), gblk>>>(p_x1, p_K, nullptr, p_att,
        LQ, LK, H2, (long)LQ * H2, (long)LK * H2, (long)LQ * LK, 0);

    // 8. masked softmax over k
    k_softmax<<<dim3(LQ, BB), 64>>>(source);

    // 9. ctx = A @ V into cat[:, :H2]  (cat[:, H2:] already holds Q from decoder cells)
    k_ctx<<<dim3(H2 / 128, LQ / 16, BB), 128>>>();

    // 10. fc1 with tanh: x1 = tanh(cat @ fc1_W^T + fc1_b)   (overwrites Q temp storage)
    k_gemm<<<dim3(H2 / 64, (BB * LQ) / 64, 1), gblk>>>(p_cat, fc1_W, fc1_b, p_x1,
        BB * LQ, H2, 2 * H2, 0, 0, 0, 1);

    // 11. fc2: out = x1 @ fc2_W^T + fc2_b
    k_gemm<<<dim3((VV + 63) / 64, (BB * LQ) / 64, 1), gblk>>>(p_x1, fc2_W, fc2_b, out,
        BB * LQ, VV, H2, 0, 0, 0, 0);
}

// round 6
// speedup vs baseline: 1.1924x; 1.1924x over previous
#include <cuda_runtime.h>
#include <math.h>

// ---------------- problem constants ----------------
#define BB   16      // batch
#define LK   64      // source length
#define LQ   64      // query length
#define DD   300     // embedding dim
#define HH   512     // encoder hidden
#define H2   1024    // 2*H (decoder hidden / enc_out channels)
#define HG   2048    // 4*H  encoder gates
#define DG   4096    // 8*H  decoder gates
#define VV   10000   // vocab
#define KSE  4       // encoder k-split
#define KSD  8       // decoder k-split

// ---------------- scratch (device globals; no allocation) ----------------
__device__ float g_xs_src[BB * LK * DD];
__device__ float g_xs_prev[BB * LQ * DD];
__device__ float g_xg_f[BB * LK * HG];
__device__ float g_xg_b[BB * LK * HG];
__device__ float g_xg_d[BB * LQ * DG];
__device__ float g_WT_f[HH * HG];     // [k<512][n<2048]
__device__ float g_WT_b[HH * HG];
__device__ float g_WT_d[H2 * DG];     // [k<1024][n<4096]
__device__ float g_he[2 * BB * HH];   // enc h (dir, b, j) — for dec init
__device__ float g_ce[2 * BB * HH];
__device__ float g_heT[2 * HH * BB];  // enc h transposed: (dir, k=j, b)
__device__ float g_cd[BB * H2];
__device__ float g_hdT[H2 * BB];      // dec h transposed: (k=jj, b)
__device__ float g_part_e[2 * KSE * BB * HG];  // k-split partials
__device__ float g_part_d[KSD * BB * DG];
__device__ float g_enc[BB * LK * H2];
__device__ float g_Kb[BB * LK * H2];
__device__ float g_Vb[BB * LK * H2];
__device__ float g_att[BB * LQ * LK];
__device__ float g_cat[BB * LQ * 2 * H2];
__device__ float g_x1[BB * LQ * H2];

__device__ __forceinline__ float sigf(float x) { return 1.f / (1.f + expf(-x)); }

// ---------------- small utility kernels ----------------
__global__ void k_zero_states() {
    int i = blockIdx.x * blockDim.x + threadIdx.x;
    int n = 2 * BB * HH;
    if (i < n) { g_he[i] = 0.f; g_ce[i] = 0.f; g_heT[i] = 0.f; }
}

__global__ void k_embed(const int* __restrict__ idx, const float* __restrict__ emb,
                        float* __restrict__ out, int rows) {
    int i = blockIdx.x * blockDim.x + threadIdx.x;
    if (i < rows * DD) {
        int r = i / DD, d = i - r * DD;
        out[i] = emb[(long)idx[r] * DD + d];
    }
}

// in[R][C] -> out[C][R]
__global__ void k_transpose(const float* __restrict__ in, float* __restrict__ out,
                            int R, int C) {
    __shared__ float tile[32][33];
    int c0 = blockIdx.x * 32, r0 = blockIdx.y * 32;
    int c = c0 + threadIdx.x;
    #pragma unroll
    for (int i = 0; i < 32; i += 8) {
        int r = r0 + threadIdx.y + i;
        if (r < R && c < C) tile[threadIdx.y + i][threadIdx.x] = in[(long)r * C + c];
    }
    __syncthreads();
    int oc = r0 + threadIdx.x;
    #pragma unroll
    for (int i = 0; i < 32; i += 8) {
        int orr = c0 + threadIdx.y + i;
        if (orr < C && oc < R) out[(long)orr * R + oc] = tile[threadIdx.x][threadIdx.y + i];
    }
}

// ---------------- big SGEMM: C[M,N] = A[M,K] @ W[N,K]^T (+bias)(+tanh) ----------------
// 128x128 tile, BK=8, 256 threads, 8x8 microtile, float4 everywhere.
// Requires K % 4 == 0 (holds: 300, 1024, 2048).
__global__ void __launch_bounds__(256, 2)
k_sgemm(const float* __restrict__ A, const float* __restrict__ W,
        const float* __restrict__ bias, float* __restrict__ C,
        int M, int N, int K, int act) {
    __shared__ float4 As4[8 * 33];   // row stride 33 float4 = 132 floats (bank-stagger)
    __shared__ float4 Ws4[8 * 33];
    int tid = threadIdx.x;
    int tx = tid & 15, ty = tid >> 4;
    int m0 = blockIdx.y * 128, n0 = blockIdx.x * 128;
    int lr = tid >> 1;            // 0..127 tile row
    int lk = (tid & 1) * 4;       // 0 or 4
    float acc[8][8] = {};
    float* Asf = (float*)As4;
    float* Wsf = (float*)Ws4;

    for (int kk = 0; kk < K; kk += 8) {
        float4 av = make_float4(0.f, 0.f, 0.f, 0.f);
        float4 wv = make_float4(0.f, 0.f, 0.f, 0.f);
        if (kk + lk < K) {
            if (m0 + lr < M) av = *(const float4*)(A + (long)(m0 + lr) * K + kk + lk);
            if (n0 + lr < N) wv = *(const float4*)(W + (long)(n0 + lr) * K + kk + lk);
        }
        __syncthreads();
        Asf[(lk + 0) * 132 + lr] = av.x; Asf[(lk + 1) * 132 + lr] = av.y;
        Asf[(lk + 2) * 132 + lr] = av.z; Asf[(lk + 3) * 132 + lr] = av.w;
        Wsf[(lk + 0) * 132 + lr] = wv.x; Wsf[(lk + 1) * 132 + lr] = wv.y;
        Wsf[(lk + 2) * 132 + lr] = wv.z; Wsf[(lk + 3) * 132 + lr] = wv.w;
        __syncthreads();
        #pragma unroll
        for (int k = 0; k < 8; k++) {
            float4 a0 = As4[k * 33 + ty];
            float4 a1 = As4[k * 33 + 16 + ty];
            float4 b0 = Ws4[k * 33 + tx];
            float4 b1 = Ws4[k * 33 + 16 + tx];
            float ar[8] = {a0.x, a0.y, a0.z, a0.w, a1.x, a1.y, a1.z, a1.w};
            float br[8] = {b0.x, b0.y, b0.z, b0.w, b1.x, b1.y, b1.z, b1.w};
            #pragma unroll
            for (int i = 0; i < 8; i++)
                #pragma unroll
                for (int j = 0; j < 8; j++) acc[i][j] += ar[i] * br[j];
        }
    }
    #pragma unroll
    for (int i = 0; i < 8; i++) {
        int m = m0 + ty * 4 + (i < 4 ? i : 60 + i);
        if (m >= M) continue;
        #pragma unroll
        for (int j = 0; j < 8; j++) {
            int n = n0 + tx * 4 + (j < 4 ? j : 60 + j);
            if (n >= N) continue;
            float v = acc[i][j];
            if (bias) v += bias[n];
            if (act == 1) v = tanhf(v);
            C[(long)m * N + n] = v;
        }
    }
}

// ---------------- small batched GEMM for attention scores (kept from R1) ----------------
__global__ void k_gemm(const float* __restrict__ A, const float* __restrict__ W,
                       const float* __restrict__ bias, float* __restrict__ C,
                       int M, int N, int K, long sA, long sW, long sC, int act) {
    A += (long)blockIdx.z * sA;
    W += (long)blockIdx.z * sW;
    C += (long)blockIdx.z * sC;
    __shared__ float As[16][68];
    __shared__ float Ws[16][68];
    int m0 = blockIdx.y * 64, n0 = blockIdx.x * 64;
    int tx = threadIdx.x, ty = threadIdx.y;
    int tid = ty * 16 + tx;
    float acc[4][4] = {};
    for (int kk = 0; kk < K; kk += 16) {
        #pragma unroll
        for (int s = 0; s < 4; s++) {
            int e = tid + s * 256;
            int mm = e >> 4, k = e & 15;
            float va = 0.f, vw = 0.f;
            if (m0 + mm < M && kk + k < K) va = A[(long)(m0 + mm) * K + kk + k];
            if (n0 + mm < N && kk + k < K) vw = W[(long)(n0 + mm) * K + kk + k];
            As[k][mm] = va;
            Ws[k][mm] = vw;
        }
        __syncthreads();
        #pragma unroll
        for (int k = 0; k < 16; k++) {
            float a[4], w[4];
            #pragma unroll
            for (int i = 0; i < 4; i++) a[i] = As[k][ty * 4 + i];
            #pragma unroll
            for (int j = 0; j < 4; j++) w[j] = Ws[k][tx * 4 + j];
            #pragma unroll
            for (int i = 0; i < 4; i++)
                #pragma unroll
                for (int j = 0; j < 4; j++) acc[i][j] += a[i] * w[j];
        }
        __syncthreads();
    }
    #pragma unroll
    for (int i = 0; i < 4; i++) {
        int m = m0 + ty * 4 + i;
        if (m >= M) continue;
        #pragma unroll
        for (int j = 0; j < 4; j++) {
            int n = n0 + tx * 4 + j;
            if (n >= N) continue;
            float v = acc[i][j];
            if (bias) v += bias[n];
            if (act == 1) v = tanhf(v);
            C[(long)m * N + n] = v;
        }
    }
}

// ---------------- encoder LSTM step: k-split matvec (all 16 batches per thread) ----
// grid (HG/128, KSE, 2), block 128. h read via transposed layout (broadcast float4).
__global__ void k_enc_matvec2() {
    int dir = blockIdx.z;
    int n = blockIdx.x * 128 + threadIdx.x;
    int k0 = blockIdx.y * (HH / KSE);
    const float* WT = (dir ? g_WT_b : g_WT_f) + (long)k0 * HG + n;
    const float4* hT = (const float4*)(g_heT + (long)dir * HH * BB + (long)k0 * BB);
    float acc[16] = {};
    #pragma unroll 4
    for (int k = 0; k < HH / KSE; k++) {
        float w = WT[(long)k * HG];
        float4 h0 = hT[k * 4 + 0], h1 = hT[k * 4 + 1];
        float4 h2 = hT[k * 4 + 2], h3 = hT[k * 4 + 3];
        acc[0]  += h0.x * w; acc[1]  += h0.y * w; acc[2]  += h0.z * w; acc[3]  += h0.w * w;
        acc[4]  += h1.x * w; acc[5]  += h1.y * w; acc[6]  += h1.z * w; acc[7]  += h1.w * w;
        acc[8]  += h2.x * w; acc[9]  += h2.y * w; acc[10] += h2.z * w; acc[11] += h2.w * w;
        acc[12] += h3.x * w; acc[13] += h3.y * w; acc[14] += h3.z * w; acc[15] += h3.w * w;
    }
    float* P = g_part_e + (long)(dir * KSE + blockIdx.y) * BB * HG + n;
    #pragma unroll
    for (int b = 0; b < 16; b++) P[(long)b * HG] = acc[b];
}

// reduce partials + input gates + LSTM cell. grid: 2*BB*HH/256 blocks
__global__ void k_enc_cell2(int t) {
    int idx = blockIdx.x * blockDim.x + threadIdx.x;
    if (idx >= 2 * BB * HH) return;
    int dir = idx / (BB * HH);
    int r = idx - dir * BB * HH;
    int b = r / HH, j = r - b * HH;
    int tt = dir ? (LK - 1 - t) : t;
    const float* xg = dir ? g_xg_b : g_xg_f;
    float gate[4];
    #pragma unroll
    for (int g = 0; g < 4; g++) {
        int n = g * HH + j;
        float s = xg[((long)b * LK + tt) * HG + n];
        #pragma unroll
        for (int ks = 0; ks < KSE; ks++)
            s += g_part_e[(long)((dir * KSE + ks) * BB + b) * HG + n];
        gate[g] = s;
    }
    int si = dir * BB * HH + b * HH + j;
    float c = sigf(gate[1]) * g_ce[si] + sigf(gate[0]) * tanhf(gate[2]);
    float h = sigf(gate[3]) * tanhf(c);
    g_ce[si] = c;
    g_he[si] = h;
    g_heT[(long)dir * HH * BB + (long)j * BB + b] = h;
    g_enc[((long)b * LK + tt) * H2 + dir * HH + j] = h;
}

// ---------------- decoder init: interleave fwd/bwd final states ----------------
__global__ void k_dec_init() {
    int idx = blockIdx.x * blockDim.x + threadIdx.x;
    if (idx >= BB * H2) return;
    int b = idx / H2, jj = idx - b * H2;
    int dir = jj & 1, j = jj >> 1;
    g_hdT[(long)jj * BB + b] = g_he[dir * BB * HH + b * HH + j];
    g_cd[idx] = g_ce[dir * BB * HH + b * HH + j];
}

// ---------------- decoder LSTM step ----------------
// grid (DG/128, KSD), block 128
__global__ void k_dec_matvec2() {
    int n = blockIdx.x * 128 + threadIdx.x;
    int k0 = blockIdx.y * (H2 / KSD);
    const float* WT = g_WT_d + (long)k0 * DG + n;
    const float4* hT = (const float4*)(g_hdT + (long)k0 * BB);
    float acc[16] = {};
    #pragma unroll 4
    for (int k = 0; k < H2 / KSD; k++) {
        float w = WT[(long)k * DG];
        float4 h0 = hT[k * 4 + 0], h1 = hT[k * 4 + 1];
        float4 h2 = hT[k * 4 + 2], h3 = hT[k * 4 + 3];
        acc[0]  += h0.x * w; acc[1]  += h0.y * w; acc[2]  += h0.z * w; acc[3]  += h0.w * w;
        acc[4]  += h1.x * w; acc[5]  += h1.y * w; acc[6]  += h1.z * w; acc[7]  += h1.w * w;
        acc[8]  += h2.x * w; acc[9]  += h2.y * w; acc[10] += h2.z * w; acc[11] += h2.w * w;
        acc[12] += h3.x * w; acc[13] += h3.y * w; acc[14] += h3.z * w; acc[15] += h3.w * w;
    }
    float* P = g_part_d + (long)blockIdx.y * BB * DG + n;
    #pragma unroll
    for (int b = 0; b < 16; b++) P[(long)b * DG] = acc[b];
}

__global__ void k_dec_cell2(int t) {
    int idx = blockIdx.x * blockDim.x + threadIdx.x;
    if (idx >= BB * H2) return;
    int b = idx / H2, j = idx - b * H2;
    float gate[4];
    #pragma unroll
    for (int g = 0; g < 4; g++) {
        int n = g * H2 + j;
        float s = g_xg_d[((long)b * LQ + t) * DG + n];
        #pragma unroll
        for (int ks = 0; ks < KSD; ks++)
            s += g_part_d[(long)(ks * BB + b) * DG + n];
        gate[g] = s;
    }
    float c = sigf(gate[1]) * g_cd[idx] + sigf(gate[0]) * tanhf(gate[2]);
    float h = sigf(gate[3]) * tanhf(c);
    g_cd[idx] = c;
    g_hdT[(long)j * BB + b] = h;
    long base = (long)b * LQ + t;
    g_cat[base * (2 * H2) + H2 + j] = h;   // Q half of fc1 concat input
    g_x1[base * H2 + j] = h;               // Q buffer for attention (fc1 overwrites later)
}

// ---------------- softmax over k with PAD mask ----------------
__global__ void k_softmax(const int* __restrict__ source) {
    int b = blockIdx.y, q = blockIdx.x;
    int k = threadIdx.x; // 64
    long off = ((long)b * LQ + q) * LK;
    float s = g_att[off + k];
    if (source[b * LK + k] == 0) s = -INFINITY;
    __shared__ float red[64];
    red[k] = s;
    __syncthreads();
    #pragma unroll
    for (int st = 32; st > 0; st >>= 1) {
        if (k < st) red[k] = fmaxf(red[k], red[k + st]);
        __syncthreads();
    }
    float mx = red[0];
    __syncthreads();
    float e = expf(s - mx);
    red[k] = e;
    __syncthreads();
    #pragma unroll
    for (int st = 32; st > 0; st >>= 1) {
        if (k < st) red[k] += red[k + st];
        __syncthreads();
    }
    g_att[off + k] = e / red[0];
}

// ---------------- ctx = A @ V into first half of concat buffer ----------------
__global__ void k_ctx() {
    int b = blockIdx.z;
    int q0 = blockIdx.y * 16;
    int c = blockIdx.x * 128 + threadIdx.x;
    __shared__ float As[16][64];
    for (int i = threadIdx.x; i < 16 * 64; i += 128)
        As[i / 64][i & 63] = g_att[((long)b * LQ + q0 + i / 64) * LK + (i & 63)];
    __syncthreads();
    float acc[16] = {};
    for (int k = 0; k < LK; k++) {
        float v = g_Vb[((long)b * LK + k) * H2 + c];
        #pragma unroll
        for (int q = 0; q < 16; q++) acc[q] += As[q][k] * v;
    }
    #pragma unroll
    for (int q = 0; q < 16; q++)
        g_cat[((long)b * LQ + q0 + q) * (2 * H2) + c] = acc[q];
}

// ---------------- host launch ----------------
extern "C" void kernel_launch(void* const* d_in, const int* in_sizes, int n_in,
                              void* d_out, int out_size) {
    const int*   source   = (const int*)  d_in[0];
    const int*   prev     = (const int*)  d_in[1];
    const float* emb      = (const float*)d_in[2];
    const float* ef_Wih   = (const float*)d_in[3];
    const float* ef_Whh   = (const float*)d_in[4];
    const float* ef_b     = (const float*)d_in[5];
    const float* eb_Wih   = (const float*)d_in[6];
    const float* eb_Whh   = (const float*)d_in[7];
    const float* eb_b     = (const float*)d_in[8];
    const float* d_Wih    = (const float*)d_in[9];
    const float* d_Whh    = (const float*)d_in[10];
    const float* d_b      = (const float*)d_in[11];
    const float* k_W      = (const float*)d_in[12];
    const float* k_b      = (const float*)d_in[13];
    const float* v_W      = (const float*)d_in[14];
    const float* v_b      = (const float*)d_in[15];
    const float* fc1_W    = (const float*)d_in[16];
    const float* fc1_b    = (const float*)d_in[17];
    const float* fc2_W    = (const float*)d_in[18];
    const float* fc2_b    = (const float*)d_in[19];
    float* out = (float*)d_out;

    float *p_xs_src, *p_xs_prev, *p_xg_f, *p_xg_b, *p_xg_d;
    float *p_WT_f, *p_WT_b, *p_WT_d, *p_enc, *p_K, *p_V, *p_att, *p_cat, *p_x1;
    cudaGetSymbolAddress((void**)&p_xs_src, g_xs_src);
    cudaGetSymbolAddress((void**)&p_xs_prev, g_xs_prev);
    cudaGetSymbolAddress((void**)&p_xg_f, g_xg_f);
    cudaGetSymbolAddress((void**)&p_xg_b, g_xg_b);
    cudaGetSymbolAddress((void**)&p_xg_d, g_xg_d);
    cudaGetSymbolAddress((void**)&p_WT_f, g_WT_f);
    cudaGetSymbolAddress((void**)&p_WT_b, g_WT_b);
    cudaGetSymbolAddress((void**)&p_WT_d, g_WT_d);
    cudaGetSymbolAddress((void**)&p_enc, g_enc);
    cudaGetSymbolAddress((void**)&p_K, g_Kb);
    cudaGetSymbolAddress((void**)&p_V, g_Vb);
    cudaGetSymbolAddress((void**)&p_att, g_att);
    cudaGetSymbolAddress((void**)&p_cat, g_cat);
    cudaGetSymbolAddress((void**)&p_x1, g_x1);

    // 0. zero encoder states
    k_zero_states<<<(2 * BB * HH + 255) / 256, 256>>>();

    // 1. embeddings
    k_embed<<<(BB * LK * DD + 255) / 256, 256>>>(source, emb, p_xs_src, BB * LK);
    k_embed<<<(BB * LQ * DD + 255) / 256, 256>>>(prev, emb, p_xs_prev, BB * LQ);

    // 2. transpose recurrent weights to k-major
    k_transpose<<<dim3((HH + 31) / 32, (HG + 31) / 32), dim3(32, 8)>>>(ef_Whh, p_WT_f, HG, HH);
    k_transpose<<<dim3((HH + 31) / 32, (HG + 31) / 32), dim3(32, 8)>>>(eb_Whh, p_WT_b, HG, HH);
    k_transpose<<<dim3((H2 + 31) / 32, (DG + 31) / 32), dim3(32, 8)>>>(d_Whh, p_WT_d, DG, H2);

    // 3. input pregates xg = xs @ Wih^T + b  (big SGEMM)
    k_sgemm<<<dim3(HG / 128, (BB * LK) / 128), 256>>>(p_xs_src, ef_Wih, ef_b, p_xg_f,
        BB * LK, HG, DD, 0);
    k_sgemm<<<dim3(HG / 128, (BB * LK) / 128), 256>>>(p_xs_src, eb_Wih, eb_b, p_xg_b,
        BB * LK, HG, DD, 0);
    k_sgemm<<<dim3(DG / 128, (BB * LQ) / 128), 256>>>(p_xs_prev, d_Wih, d_b, p_xg_d,
        BB * LQ, DG, DD, 0);

    // 4. encoder recurrence (fwd + bwd fused per step, k-split matvec + reduce/cell)
    for (int t = 0; t < LK; t++) {
        k_enc_matvec2<<<dim3(HG / 128, KSE, 2), 128>>>();
        k_enc_cell2<<<(2 * BB * HH + 255) / 256, 256>>>(t);
    }

    // 5. decoder init + recurrence
    k_dec_init<<<(BB * H2 + 255) / 256, 256>>>();
    for (int t = 0; t < LQ; t++) {
        k_dec_matvec2<<<dim3(DG / 128, KSD), 128>>>();
        k_dec_cell2<<<(BB * H2 + 255) / 256, 256>>>(t);
    }

    // 6. K and V projections on enc_out
    k_sgemm<<<dim3(H2 / 128, (BB * LK) / 128), 256>>>(p_enc, k_W, k_b, p_K,
        BB * LK, H2, H2, 0);
    k_sgemm<<<dim3(H2 / 128, (BB * LK) / 128), 256>>>(p_enc, v_W, v_b, p_V,
        BB * LK, H2, H2, 0);

    // 7. scores M[b,q,k] = Q[b,q,:] · K[b,k,:]   (Q stored in g_x1)
    k_gemm<<<dim3(1, 1, BB), dim3(16, 16)>>>(p_x1, p_K, nullptr, p_att,
        LQ, LK, H2, (long)LQ * H2, (long)LK * H2, (long)LQ * LK, 0);

    // 8. masked softmax over k
    k_softmax<<<dim3(LQ, BB), 64>>>(source);

    // 9. ctx = A @ V into cat[:, :H2]  (cat[:, H2:] holds Q from decoder cells)
    k_ctx<<<dim3(H2 / 128, LQ / 16, BB), 128>>>();

    // 10. fc1 with tanh (overwrites Q temp storage in g_x1)
    k_sgemm<<<dim3(H2 / 128, (BB * LQ) / 128), 256>>>(p_cat, fc1_W, fc1_b, p_x1,
        BB * LQ, H2, 2 * H2, 1);

    // 11. fc2: out = x1 @ fc2_W^T + fc2_b
    k_sgemm<<<dim3((VV + 127) / 128, (BB * LQ) / 128), 256>>>(p_x1, fc2_W, fc2_b, out,
        BB * LQ, VV, H2, 0);
}

// round 7
// speedup vs baseline: 2.3069x; 1.9346x over previous
#include <cuda_runtime.h>
#include <math.h>

// ---------------- problem constants ----------------
#define BB   16      // batch
#define LK   64      // source length
#define LQ   64      // query length
#define DD   300     // embedding dim
#define HH   512     // encoder hidden
#define H2   1024    // 2*H (decoder hidden / enc_out channels)
#define HG   2048    // 4*H  encoder gates
#define DG   4096    // 8*H  decoder gates
#define VV   10000   // vocab
#define KS   8       // k-split (both enc and dec)

#define NBLK 128
#define NTHR 256

// ---------------- scratch (device globals; no allocation) ----------------
__device__ float g_xs_src[BB * LK * DD];
__device__ float g_xs_prev[BB * LQ * DD];
__device__ float g_xg_f[BB * LK * HG];
__device__ float g_xg_b[BB * LK * HG];
__device__ float g_xg_d[BB * LQ * DG];
__device__ float g_WT_f[HH * HG];     // [k<512][n<2048]
__device__ float g_WT_b[HH * HG];
__device__ float g_WT_d[H2 * DG];     // [k<1024][n<4096]
__device__ float g_ce[2 * BB * HH];
__device__ float g_heT[2 * HH * BB];  // enc h transposed: (dir, k=j, b)
__device__ float g_cd[BB * H2];
__device__ float g_hdT[H2 * BB];      // dec h transposed: (k=jj, b)
__device__ float g_part_e[2 * KS * BB * HG];  // k-split partials
__device__ float g_part_d[KS * BB * DG];
__device__ float g_enc[BB * LK * H2];
__device__ float g_Kb[BB * LK * H2];
__device__ float g_Vb[BB * LK * H2];
__device__ float g_att[BB * LQ * LK];
__device__ float g_cat[BB * LQ * 2 * H2];
__device__ float g_x1[BB * LQ * H2];

// grid barrier state (generation counter; self-resetting, replay-safe)
__device__ unsigned g_bar_cnt = 0;
__device__ unsigned g_bar_gen = 0;

__device__ __forceinline__ float sigf(float x) { return 1.f / (1.f + expf(-x)); }

__device__ __forceinline__ void gbar() {
    __syncthreads();
    if (threadIdx.x == 0) {
        volatile unsigned* genp = &g_bar_gen;
        __threadfence();
        unsigned g = *genp;
        if (atomicAdd(&g_bar_cnt, 1u) == NBLK - 1) {
            g_bar_cnt = 0;
            __threadfence();
            *genp = g + 1;
        } else {
            while (*genp == g) { }
            __threadfence();
        }
    }
    __syncthreads();
}

// ---------------- small utility kernels ----------------
__global__ void k_zero_states() {
    int i = blockIdx.x * blockDim.x + threadIdx.x;
    int n = 2 * BB * HH;
    if (i < n) { g_ce[i] = 0.f; g_heT[i] = 0.f; }
}

__global__ void k_embed(const int* __restrict__ idx, const float* __restrict__ emb,
                        float* __restrict__ out, int rows) {
    int i = blockIdx.x * blockDim.x + threadIdx.x;
    if (i < rows * DD) {
        int r = i / DD, d = i - r * DD;
        out[i] = emb[(long)idx[r] * DD + d];
    }
}

// in[R][C] -> out[C][R]
__global__ void k_transpose(const float* __restrict__ in, float* __restrict__ out,
                            int R, int C) {
    __shared__ float tile[32][33];
    int c0 = blockIdx.x * 32, r0 = blockIdx.y * 32;
    int c = c0 + threadIdx.x;
    #pragma unroll
    for (int i = 0; i < 32; i += 8) {
        int r = r0 + threadIdx.y + i;
        if (r < R && c < C) tile[threadIdx.y + i][threadIdx.x] = in[(long)r * C + c];
    }
    __syncthreads();
    int oc = r0 + threadIdx.x;
    #pragma unroll
    for (int i = 0; i < 32; i += 8) {
        int orr = c0 + threadIdx.y + i;
        if (orr < C && oc < R) out[(long)orr * R + oc] = tile[threadIdx.x][threadIdx.y + i];
    }
}

// ---------------- big SGEMM: C[M,N] = A[M,K] @ W[N,K]^T (+bias)(+tanh) ----------------
__global__ void __launch_bounds__(256, 2)
k_sgemm(const float* __restrict__ A, const float* __restrict__ W,
        const float* __restrict__ bias, float* __restrict__ C,
        int M, int N, int K, int act) {
    __shared__ float4 As4[8 * 33];
    __shared__ float4 Ws4[8 * 33];
    int tid = threadIdx.x;
    int tx = tid & 15, ty = tid >> 4;
    int m0 = blockIdx.y * 128, n0 = blockIdx.x * 128;
    int lr = tid >> 1;
    int lk = (tid & 1) * 4;
    float acc[8][8] = {};
    float* Asf = (float*)As4;
    float* Wsf = (float*)Ws4;

    for (int kk = 0; kk < K; kk += 8) {
        float4 av = make_float4(0.f, 0.f, 0.f, 0.f);
        float4 wv = make_float4(0.f, 0.f, 0.f, 0.f);
        if (kk + lk < K) {
            if (m0 + lr < M) av = *(const float4*)(A + (long)(m0 + lr) * K + kk + lk);
            if (n0 + lr < N) wv = *(const float4*)(W + (long)(n0 + lr) * K + kk + lk);
        }
        __syncthreads();
        Asf[(lk + 0) * 132 + lr] = av.x; Asf[(lk + 1) * 132 + lr] = av.y;
        Asf[(lk + 2) * 132 + lr] = av.z; Asf[(lk + 3) * 132 + lr] = av.w;
        Wsf[(lk + 0) * 132 + lr] = wv.x; Wsf[(lk + 1) * 132 + lr] = wv.y;
        Wsf[(lk + 2) * 132 + lr] = wv.z; Wsf[(lk + 3) * 132 + lr] = wv.w;
        __syncthreads();
        #pragma unroll
        for (int k = 0; k < 8; k++) {
            float4 a0 = As4[k * 33 + ty];
            float4 a1 = As4[k * 33 + 16 + ty];
            float4 b0 = Ws4[k * 33 + tx];
            float4 b1 = Ws4[k * 33 + 16 + tx];
            float ar[8] = {a0.x, a0.y, a0.z, a0.w, a1.x, a1.y, a1.z, a1.w};
            float br[8] = {b0.x, b0.y, b0.z, b0.w, b1.x, b1.y, b1.z, b1.w};
            #pragma unroll
            for (int i = 0; i < 8; i++)
                #pragma unroll
                for (int j = 0; j < 8; j++) acc[i][j] += ar[i] * br[j];
        }
    }
    #pragma unroll
    for (int i = 0; i < 8; i++) {
        int m = m0 + ty * 4 + (i < 4 ? i : 60 + i);
        if (m >= M) continue;
        #pragma unroll
        for (int j = 0; j < 8; j++) {
            int n = n0 + tx * 4 + (j < 4 ? j : 60 + j);
            if (n >= N) continue;
            float v = acc[i][j];
            if (bias) v += bias[n];
            if (act == 1) v = tanhf(v);
            C[(long)m * N + n] = v;
        }
    }
}

// ---------------- small batched GEMM for attention scores ----------------
__global__ void k_gemm(const float* __restrict__ A, const float* __restrict__ W,
                       const float* __restrict__ bias, float* __restrict__ C,
                       int M, int N, int K, long sA, long sW, long sC, int act) {
    A += (long)blockIdx.z * sA;
    W += (long)blockIdx.z * sW;
    C += (long)blockIdx.z * sC;
    __shared__ float As[16][68];
    __shared__ float Ws[16][68];
    int m0 = blockIdx.y * 64, n0 = blockIdx.x * 64;
    int tx = threadIdx.x, ty = threadIdx.y;
    int tid = ty * 16 + tx;
    float acc[4][4] = {};
    for (int kk = 0; kk < K; kk += 16) {
        #pragma unroll
        for (int s = 0; s < 4; s++) {
            int e = tid + s * 256;
            int mm = e >> 4, k = e & 15;
            float va = 0.f, vw = 0.f;
            if (m0 + mm < M && kk + k < K) va = A[(long)(m0 + mm) * K + kk + k];
            if (n0 + mm < N && kk + k < K) vw = W[(long)(n0 + mm) * K + kk + k];
            As[k][mm] = va;
            Ws[k][mm] = vw;
        }
        __syncthreads();
        #pragma unroll
        for (int k = 0; k < 16; k++) {
            float a[4], w[4];
            #pragma unroll
            for (int i = 0; i < 4; i++) a[i] = As[k][ty * 4 + i];
            #pragma unroll
            for (int j = 0; j < 4; j++) w[j] = Ws[k][tx * 4 + j];
            #pragma unroll
            for (int i = 0; i < 4; i++)
                #pragma unroll
                for (int j = 0; j < 4; j++) acc[i][j] += a[i] * w[j];
        }
        __syncthreads();
    }
    #pragma unroll
    for (int i = 0; i < 4; i++) {
        int m = m0 + ty * 4 + i;
        if (m >= M) continue;
        #pragma unroll
        for (int j = 0; j < 4; j++) {
            int n = n0 + tx * 4 + j;
            if (n >= N) continue;
            float v = acc[i][j];
            if (bias) v += bias[n];
            if (act == 1) v = tanhf(v);
            C[(long)m * N + n] = v;
        }
    }
}

// ---------------- persistent recurrence kernel ----------------
// 128 blocks x 256 threads, all co-resident. Encoder 64 steps, dec init,
// decoder 64 steps; grid barriers between phases.
__global__ void __launch_bounds__(NTHR, 1) k_recurrence() {
    __shared__ float sh[2048];   // h chunk: enc 64*16, dec 128*16 floats
    const int tid = blockIdx.x * NTHR + threadIdx.x;   // 0..32767

    // ===================== encoder =====================
    {
        // block-uniform task bits (tid>>11 constant within a 256-thread block)
        const int hi  = tid >> 11;        // 0..15 = dir*8 + ks
        const int ks  = hi & 7;
        const int dir = hi >> 3;
        const int n   = tid & (HG - 1);
        const int k0  = ks * (HH / KS);   // chunk of 64 k's
        const float* WT = (dir ? g_WT_b : g_WT_f) + (long)k0 * HG + n;
        const float* hTsrc = g_heT + (long)dir * HH * BB + (long)k0 * BB;
        float* P = g_part_e + (long)hi * BB * HG + n;

        for (int t = 0; t < LK; t++) {
            // stage h chunk (64 k x 16 b = 1024 floats) into smem
            for (int i = threadIdx.x; i < (HH / KS) * BB; i += NTHR)
                sh[i] = hTsrc[i];
            __syncthreads();
            float acc[16] = {};
            #pragma unroll 4
            for (int k = 0; k < HH / KS; k++) {
                float w = WT[(long)k * HG];
                const float4* h4 = (const float4*)(sh + k * BB);
                float4 h0 = h4[0], h1 = h4[1], h2 = h4[2], h3 = h4[3];
                acc[0]  += h0.x * w; acc[1]  += h0.y * w; acc[2]  += h0.z * w; acc[3]  += h0.w * w;
                acc[4]  += h1.x * w; acc[5]  += h1.y * w; acc[6]  += h1.z * w; acc[7]  += h1.w * w;
                acc[8]  += h2.x * w; acc[9]  += h2.y * w; acc[10] += h2.z * w; acc[11] += h2.w * w;
                acc[12] += h3.x * w; acc[13] += h3.y * w; acc[14] += h3.z * w; acc[15] += h3.w * w;
            }
            #pragma unroll
            for (int b = 0; b < 16; b++) P[(long)b * HG] = acc[b];
            gbar();

            // ---- cell: 2*BB*HH = 16384 elements ----
            if (tid < 2 * BB * HH) {
                int cdir = tid >> 13;
                int r = tid & (BB * HH - 1);
                int b = r >> 9, j = r & (HH - 1);
                int tt = cdir ? (LK - 1 - t) : t;
                const float* xg = cdir ? g_xg_b : g_xg_f;
                float gate[4];
                #pragma unroll
                for (int g = 0; g < 4; g++) {
                    int nn = g * HH + j;
                    float s = xg[((long)b * LK + tt) * HG + nn];
                    #pragma unroll
                    for (int q = 0; q < KS; q++)
                        s += g_part_e[(long)(cdir * KS + q) * BB * HG + (long)b * HG + nn];
                    gate[g] = s;
                }
                int si = cdir * BB * HH + b * HH + j;
                float c = sigf(gate[1]) * g_ce[si] + sigf(gate[0]) * tanhf(gate[2]);
                float h = sigf(gate[3]) * tanhf(c);
                g_ce[si] = c;
                g_heT[(long)cdir * HH * BB + (long)j * BB + b] = h;
                g_enc[((long)b * LK + tt) * H2 + cdir * HH + j] = h;
            }
            gbar();
        }
    }

    // ===================== decoder init =====================
    if (tid < BB * H2) {
        int b = tid >> 10, jj = tid & (H2 - 1);
        int dir = jj & 1, j = jj >> 1;
        g_hdT[(long)jj * BB + b] = g_heT[(long)dir * HH * BB + (long)j * BB + b];
        g_cd[tid] = g_ce[dir * BB * HH + b * HH + j];
    }
    gbar();

    // ===================== decoder =====================
    {
        const int ks = tid >> 12;         // 0..7, block-uniform
        const int n  = tid & (DG - 1);
        const int k0 = ks * (H2 / KS);    // chunk of 128 k's
        const float* WT = g_WT_d + (long)k0 * DG + n;
        const float* hTsrc = g_hdT + (long)k0 * BB;
        float* P = g_part_d + (long)ks * BB * DG + n;

        for (int t = 0; t < LQ; t++) {
            for (int i = threadIdx.x; i < (H2 / KS) * BB; i += NTHR)
                sh[i] = hTsrc[i];
            __syncthreads();
            float acc[16] = {};
            #pragma unroll 4
            for (int k = 0; k < H2 / KS; k++) {
                float w = WT[(long)k * DG];
                const float4* h4 = (const float4*)(sh + k * BB);
                float4 h0 = h4[0], h1 = h4[1], h2 = h4[2], h3 = h4[3];
                acc[0]  += h0.x * w; acc[1]  += h0.y * w; acc[2]  += h0.z * w; acc[3]  += h0.w * w;
                acc[4]  += h1.x * w; acc[5]  += h1.y * w; acc[6]  += h1.z * w; acc[7]  += h1.w * w;
                acc[8]  += h2.x * w; acc[9]  += h2.y * w; acc[10] += h2.z * w; acc[11] += h2.w * w;
                acc[12] += h3.x * w; acc[13] += h3.y * w; acc[14] += h3.z * w; acc[15] += h3.w * w;
            }
            #pragma unroll
            for (int b = 0; b < 16; b++) P[(long)b * DG] = acc[b];
            gbar();

            // ---- cell: BB*H2 = 16384 elements ----
            if (tid < BB * H2) {
                int b = tid >> 10, j = tid & (H2 - 1);
                float gate[4];
                #pragma unroll
                for (int g = 0; g < 4; g++) {
                    int nn = g * H2 + j;
                    float s = g_xg_d[((long)b * LQ + t) * DG + nn];
                    #pragma unroll
                    for (int q = 0; q < KS; q++)
                        s += g_part_d[(long)q * BB * DG + (long)b * DG + nn];
                    gate[g] = s;
                }
                float c = sigf(gate[1]) * g_cd[tid] + sigf(gate[0]) * tanhf(gate[2]);
                float h = sigf(gate[3]) * tanhf(c);
                g_cd[tid] = c;
                g_hdT[(long)j * BB + b] = h;
                long base = (long)b * LQ + t;
                g_cat[base * (2 * H2) + H2 + j] = h;   // Q half of fc1 concat
                g_x1[base * H2 + j] = h;               // Q for attention
            }
            gbar();
        }
    }
}

// ---------------- softmax over k with PAD mask ----------------
__global__ void k_softmax(const int* __restrict__ source) {
    int b = blockIdx.y, q = blockIdx.x;
    int k = threadIdx.x; // 64
    long off = ((long)b * LQ + q) * LK;
    float s = g_att[off + k];
    if (source[b * LK + k] == 0) s = -INFINITY;
    __shared__ float red[64];
    red[k] = s;
    __syncthreads();
    #pragma unroll
    for (int st = 32; st > 0; st >>= 1) {
        if (k < st) red[k] = fmaxf(red[k], red[k + st]);
        __syncthreads();
    }
    float mx = red[0];
    __syncthreads();
    float e = expf(s - mx);
    red[k] = e;
    __syncthreads();
    #pragma unroll
    for (int st = 32; st > 0; st >>= 1) {
        if (k < st) red[k] += red[k + st];
        __syncthreads();
    }
    g_att[off + k] = e / red[0];
}

// ---------------- ctx = A @ V into first half of concat buffer ----------------
__global__ void k_ctx() {
    int b = blockIdx.z;
    int q0 = blockIdx.y * 16;
    int c = blockIdx.x * 128 + threadIdx.x;
    __shared__ float As[16][64];
    for (int i = threadIdx.x; i < 16 * 64; i += 128)
        As[i / 64][i & 63] = g_att[((long)b * LQ + q0 + i / 64) * LK + (i & 63)];
    __syncthreads();
    float acc[16] = {};
    for (int k = 0; k < LK; k++) {
        float v = g_Vb[((long)b * LK + k) * H2 + c];
        #pragma unroll
        for (int q = 0; q < 16; q++) acc[q] += As[q][k] * v;
    }
    #pragma unroll
    for (int q = 0; q < 16; q++)
        g_cat[((long)b * LQ + q0 + q) * (2 * H2) + c] = acc[q];
}

// ---------------- host launch ----------------
extern "C" void kernel_launch(void* const* d_in, const int* in_sizes, int n_in,
                              void* d_out, int out_size) {
    const int*   source   = (const int*)  d_in[0];
    const int*   prev     = (const int*)  d_in[1];
    const float* emb      = (const float*)d_in[2];
    const float* ef_Wih   = (const float*)d_in[3];
    const float* ef_Whh   = (const float*)d_in[4];
    const float* ef_b     = (const float*)d_in[5];
    const float* eb_Wih   = (const float*)d_in[6];
    const float* eb_Whh   = (const float*)d_in[7];
    const float* eb_b     = (const float*)d_in[8];
    const float* d_Wih    = (const float*)d_in[9];
    const float* d_Whh    = (const float*)d_in[10];
    const float* d_b      = (const float*)d_in[11];
    const float* k_W      = (const float*)d_in[12];
    const float* k_b      = (const float*)d_in[13];
    const float* v_W      = (const float*)d_in[14];
    const float* v_b      = (const float*)d_in[15];
    const float* fc1_W    = (const float*)d_in[16];
    const float* fc1_b    = (const float*)d_in[17];
    const float* fc2_W    = (const float*)d_in[18];
    const float* fc2_b    = (const float*)d_in[19];
    float* out = (float*)d_out;

    float *p_xs_src, *p_xs_prev, *p_xg_f, *p_xg_b, *p_xg_d;
    float *p_WT_f, *p_WT_b, *p_WT_d, *p_enc, *p_K, *p_V, *p_att, *p_cat, *p_x1;
    cudaGetSymbolAddress((void**)&p_xs_src, g_xs_src);
    cudaGetSymbolAddress((void**)&p_xs_prev, g_xs_prev);
    cudaGetSymbolAddress((void**)&p_xg_f, g_xg_f);
    cudaGetSymbolAddress((void**)&p_xg_b, g_xg_b);
    cudaGetSymbolAddress((void**)&p_xg_d, g_xg_d);
    cudaGetSymbolAddress((void**)&p_WT_f, g_WT_f);
    cudaGetSymbolAddress((void**)&p_WT_b, g_WT_b);
    cudaGetSymbolAddress((void**)&p_WT_d, g_WT_d);
    cudaGetSymbolAddress((void**)&p_enc, g_enc);
    cudaGetSymbolAddress((void**)&p_K, g_Kb);
    cudaGetSymbolAddress((void**)&p_V, g_Vb);
    cudaGetSymbolAddress((void**)&p_att, g_att);
    cudaGetSymbolAddress((void**)&p_cat, g_cat);
    cudaGetSymbolAddress((void**)&p_x1, g_x1);

    // 0. zero encoder states
    k_zero_states<<<(2 * BB * HH + 255) / 256, 256>>>();

    // 1. embeddings
    k_embed<<<(BB * LK * DD + 255) / 256, 256>>>(source, emb, p_xs_src, BB * LK);
    k_embed<<<(BB * LQ * DD + 255) / 256, 256>>>(prev, emb, p_xs_prev, BB * LQ);

    // 2. transpose recurrent weights to k-major
    k_transpose<<<dim3((HH + 31) / 32, (HG + 31) / 32), dim3(32, 8)>>>(ef_Whh, p_WT_f, HG, HH);
    k_transpose<<<dim3((HH + 31) / 32, (HG + 31) / 32), dim3(32, 8)>>>(eb_Whh, p_WT_b, HG, HH);
    k_transpose<<<dim3((H2 + 31) / 32, (DG + 31) / 32), dim3(32, 8)>>>(d_Whh, p_WT_d, DG, H2);

    // 3. input pregates xg = xs @ Wih^T + b
    k_sgemm<<<dim3(HG / 128, (BB * LK) / 128), 256>>>(p_xs_src, ef_Wih, ef_b, p_xg_f,
        BB * LK, HG, DD, 0);
    k_sgemm<<<dim3(HG / 128, (BB * LK) / 128), 256>>>(p_xs_src, eb_Wih, eb_b, p_xg_b,
        BB * LK, HG, DD, 0);
    k_sgemm<<<dim3(DG / 128, (BB * LQ) / 128), 256>>>(p_xs_prev, d_Wih, d_b, p_xg_d,
        BB * LQ, DG, DD, 0);

    // 4+5. full recurrence in ONE persistent kernel
    k_recurrence<<<NBLK, NTHR>>>();

    // 6. K and V projections on enc_out
    k_sgemm<<<dim3(H2 / 128, (BB * LK) / 128), 256>>>(p_enc, k_W, k_b, p_K,
        BB * LK, H2, H2, 0);
    k_sgemm<<<dim3(H2 / 128, (BB * LK) / 128), 256>>>(p_enc, v_W, v_b, p_V,
        BB * LK, H2, H2, 0);

    // 7. scores M[b,q,k] = Q[b,q,:] · K[b,k,:]   (Q stored in g_x1)
    k_gemm<<<dim3(1, 1, BB), dim3(16, 16)>>>(p_x1, p_K, nullptr, p_att,
        LQ, LK, H2, (long)LQ * H2, (long)LK * H2, (long)LQ * LK, 0);

    // 8. masked softmax over k
    k_softmax<<<dim3(LQ, BB), 64>>>(source);

    // 9. ctx = A @ V into cat[:, :H2]
    k_ctx<<<dim3(H2 / 128, LQ / 16, BB), 128>>>();

    // 10. fc1 with tanh (overwrites Q temp storage in g_x1)
    k_sgemm<<<dim3(H2 / 128, (BB * LQ) / 128), 256>>>(p_cat, fc1_W, fc1_b, p_x1,
        BB * LQ, H2, 2 * H2, 1);

    // 11. fc2: out = x1 @ fc2_W^T + fc2_b
    k_sgemm<<<dim3((VV + 127) / 128, (BB * LQ) / 128), 256>>>(p_x1, fc2_W, fc2_b, out,
        BB * LQ, VV, H2, 0);
}

// round 9
// speedup vs baseline: 2.4405x; 1.0579x over previous
#include <cuda_runtime.h>
#include <math.h>

// ---------------- problem constants ----------------
#define BB   16      // batch
#define LK   64      // source length
#define LQ   64      // query length
#define DD   300     // embedding dim
#define HH   512     // encoder hidden
#define H2   1024    // 2*H (decoder hidden / enc_out channels)
#define HG   2048    // 4*H  encoder gates
#define DG   4096    // 8*H  decoder gates
#define VV   10000   // vocab
#define KS   8       // k-split (both enc and dec)

#define NBLK 128
#define NTHR 256

// ---------------- scratch (device globals; no allocation) ----------------
__device__ float g_xs_src[BB * LK * DD];
__device__ float g_xs_prev[BB * LQ * DD];
__device__ float g_xg_f[BB * LK * HG];
__device__ float g_xg_b[BB * LK * HG];
__device__ float g_xg_d[BB * LQ * DG];
__device__ float g_WT_f[HH * HG];     // [k<512][n<2048]
__device__ float g_WT_b[HH * HG];
__device__ float g_WT_d[H2 * DG];     // [k<1024][n<4096]
__device__ float g_ce[2 * BB * HH];
__device__ float g_heT[2 * HH * BB];  // enc h transposed: (dir, k=j, b)
__device__ float g_cd[BB * H2];
__device__ float g_hdT[H2 * BB];      // dec h transposed: (k=jj, b)
__device__ float g_part_e[2 * KS * BB * HG];  // k-split partials
__device__ float g_part_d[KS * BB * DG];
__device__ float g_enc[BB * LK * H2];
__device__ float g_Kb[BB * LK * H2];
__device__ float g_Vb[BB * LK * H2];
__device__ float g_att[BB * LQ * LK];
__device__ float g_cat[BB * LQ * 2 * H2];
__device__ float g_x1[BB * LQ * H2];

// grid barrier state (generation counter; self-resetting, replay-safe)
__device__ unsigned g_bar_cnt = 0;
__device__ unsigned g_bar_gen = 0;

__device__ __forceinline__ float sigf(float x) { return 1.f / (1.f + expf(-x)); }

__device__ __forceinline__ void gbar() {
    __syncthreads();
    if (threadIdx.x == 0) {
        volatile unsigned* genp = &g_bar_gen;
        __threadfence();
        unsigned g = *genp;
        if (atomicAdd(&g_bar_cnt, 1u) == NBLK - 1) {
            g_bar_cnt = 0;
            __threadfence();
            *genp = g + 1;
        } else {
            while (*genp == g) { }
            __threadfence();
        }
    }
    __syncthreads();
}

// ---------------- tf32 helpers ----------------
__device__ __forceinline__ unsigned f2tf32(float f) {
    unsigned r;
    asm("cvt.rna.tf32.f32 %0, %1;" : "=r"(r) : "f"(f));
    return r;
}

__device__ __forceinline__ void mma1688(float c[4], const unsigned a[4], const unsigned b[2]) {
    asm volatile(
        "mma.sync.aligned.m16n8k8.row.col.f32.tf32.tf32.f32 "
        "{%0,%1,%2,%3}, {%4,%5,%6,%7}, {%8,%9}, {%0,%1,%2,%3};"
        : "+f"(c[0]), "+f"(c[1]), "+f"(c[2]), "+f"(c[3])
        : "r"(a[0]), "r"(a[1]), "r"(a[2]), "r"(a[3]), "r"(b[0]), "r"(b[1]));
}

// ---------------- small utility kernels ----------------
__global__ void k_zero_states() {
    int i = blockIdx.x * blockDim.x + threadIdx.x;
    int n = 2 * BB * HH;
    if (i < n) { g_ce[i] = 0.f; g_heT[i] = 0.f; }
}

__global__ void k_embed(const int* __restrict__ idx, const float* __restrict__ emb,
                        float* __restrict__ out, int rows) {
    int i = blockIdx.x * blockDim.x + threadIdx.x;
    if (i < rows * DD) {
        int r = i / DD, d = i - r * DD;
        out[i] = emb[(long)idx[r] * DD + d];
    }
}

// in[R][C] -> out[C][R]
__global__ void k_transpose(const float* __restrict__ in, float* __restrict__ out,
                            int R, int C) {
    __shared__ float tile[32][33];
    int c0 = blockIdx.x * 32, r0 = blockIdx.y * 32;
    int c = c0 + threadIdx.x;
    #pragma unroll
    for (int i = 0; i < 32; i += 8) {
        int r = r0 + threadIdx.y + i;
        if (r < R && c < C) tile[threadIdx.y + i][threadIdx.x] = in[(long)r * C + c];
    }
    __syncthreads();
    int oc = r0 + threadIdx.x;
    #pragma unroll
    for (int i = 0; i < 32; i += 8) {
        int orr = c0 + threadIdx.y + i;
        if (orr < C && oc < R) out[(long)orr * R + oc] = tile[threadIdx.x][threadIdx.y + i];
    }
}

// ---------------- tf32 tensor-core GEMM: C[M,N] = A[M,K] @ W[N,K]^T (+bias)(+tanh) ----
// 128x128 tile, BK=32, 256 threads = 8 warps (2m x 4n), warp tile 64x32,
// mma.sync m16n8k8 tf32, fp32 accumulate.
#define ASTRIDE 36
__global__ void __launch_bounds__(256, 1)
k_tgemm(const float* __restrict__ A, const float* __restrict__ W,
        const float* __restrict__ bias, float* __restrict__ C,
        int M, int N, int K, int act) {
    __shared__ unsigned As[128 * ASTRIDE];   // [m][k], padded
    __shared__ unsigned Ws[128 * ASTRIDE];   // [n][k], padded
    const int tid = threadIdx.x;
    const int warp = tid >> 5, lane = tid & 31;
    const int wm = warp >> 2, wn = warp & 3;   // 2 x 4 warp grid
    const int gid = lane >> 2, tig = lane & 3;
    const int m0 = blockIdx.y * 128, n0 = blockIdx.x * 128;
    float acc[4][4][4] = {};   // [mi][ni][creg]

    for (int kk = 0; kk < K; kk += 32) {
        __syncthreads();
        #pragma unroll
        for (int s = 0; s < 4; s++) {
            int idx = tid + s * 256;          // 0..1023
            int row = idx >> 3, c4 = (idx & 7) * 4;
            float4 va = make_float4(0.f, 0.f, 0.f, 0.f);
            if (m0 + row < M) {
                if (kk + c4 + 3 < K) {
                    va = *(const float4*)(A + (long)(m0 + row) * K + kk + c4);
                } else {
                    const float* p = A + (long)(m0 + row) * K;
                    float t0 = (kk + c4 + 0 < K) ? p[kk + c4 + 0] : 0.f;
                    float t1 = (kk + c4 + 1 < K) ? p[kk + c4 + 1] : 0.f;
                    float t2 = (kk + c4 + 2 < K) ? p[kk + c4 + 2] : 0.f;
                    float t3 = (kk + c4 + 3 < K) ? p[kk + c4 + 3] : 0.f;
                    va = make_float4(t0, t1, t2, t3);
                }
            }
            uint4 ua;
            ua.x = f2tf32(va.x); ua.y = f2tf32(va.y);
            ua.z = f2tf32(va.z); ua.w = f2tf32(va.w);
            *(uint4*)(As + row * ASTRIDE + c4) = ua;

            float4 vw = make_float4(0.f, 0.f, 0.f, 0.f);
            if (n0 + row < N) {
                if (kk + c4 + 3 < K) {
                    vw = *(const float4*)(W + (long)(n0 + row) * K + kk + c4);
                } else {
                    const float* p = W + (long)(n0 + row) * K;
                    float t0 = (kk + c4 + 0 < K) ? p[kk + c4 + 0] : 0.f;
                    float t1 = (kk + c4 + 1 < K) ? p[kk + c4 + 1] : 0.f;
                    float t2 = (kk + c4 + 2 < K) ? p[kk + c4 + 2] : 0.f;
                    float t3 = (kk + c4 + 3 < K) ? p[kk + c4 + 3] : 0.f;
                    vw = make_float4(t0, t1, t2, t3);
                }
            }
            uint4 uw;
            uw.x = f2tf32(vw.x); uw.y = f2tf32(vw.y);
            uw.z = f2tf32(vw.z); uw.w = f2tf32(vw.w);
            *(uint4*)(Ws + row * ASTRIDE + c4) = uw;
        }
        __syncthreads();

        #pragma unroll
        for (int ki = 0; ki < 4; ki++) {
            const int k0 = ki * 8;
            unsigned a[4][4], b[4][2];
            #pragma unroll
            for (int mi = 0; mi < 4; mi++) {
                int mr = wm * 64 + mi * 16;
                a[mi][0] = As[(mr + gid)     * ASTRIDE + k0 + tig];
                a[mi][1] = As[(mr + gid + 8) * ASTRIDE + k0 + tig];
                a[mi][2] = As[(mr + gid)     * ASTRIDE + k0 + tig + 4];
                a[mi][3] = As[(mr + gid + 8) * ASTRIDE + k0 + tig + 4];
            }
            #pragma unroll
            for (int ni = 0; ni < 4; ni++) {
                int nr = wn * 32 + ni * 8;
                b[ni][0] = Ws[(nr + gid) * ASTRIDE + k0 + tig];
                b[ni][1] = Ws[(nr + gid) * ASTRIDE + k0 + tig + 4];
            }
            #pragma unroll
            for (int mi = 0; mi < 4; mi++)
                #pragma unroll
                for (int ni = 0; ni < 4; ni++)
                    mma1688(acc[mi][ni], a[mi], b[ni]);
        }
    }

    // epilogue
    #pragma unroll
    for (int mi = 0; mi < 4; mi++) {
        int m1 = m0 + wm * 64 + mi * 16 + gid;
        int m2 = m1 + 8;
        #pragma unroll
        for (int ni = 0; ni < 4; ni++) {
            int nc = n0 + wn * 32 + ni * 8 + 2 * tig;
            float b0 = 0.f, b1 = 0.f;
            if (bias) {
                if (nc < N)     b0 = bias[nc];
                if (nc + 1 < N) b1 = bias[nc + 1];
            }
            float v0 = acc[mi][ni][0] + b0;
            float v1 = acc[mi][ni][1] + b1;
            float v2 = acc[mi][ni][2] + b0;
            float v3 = acc[mi][ni][3] + b1;
            if (act == 1) { v0 = tanhf(v0); v1 = tanhf(v1); v2 = tanhf(v2); v3 = tanhf(v3); }
            if (m1 < M) {
                if (nc < N)     C[(long)m1 * N + nc]     = v0;
                if (nc + 1 < N) C[(long)m1 * N + nc + 1] = v1;
            }
            if (m2 < M) {
                if (nc < N)     C[(long)m2 * N + nc]     = v2;
                if (nc + 1 < N) C[(long)m2 * N + nc + 1] = v3;
            }
        }
    }
}

// ---------------- small batched GEMM for attention scores (fp32) ----------------
__global__ void k_gemm(const float* __restrict__ A, const float* __restrict__ W,
                       const float* __restrict__ bias, float* __restrict__ C,
                       int M, int N, int K, long sA, long sW, long sC, int act) {
    A += (long)blockIdx.z * sA;
    W += (long)blockIdx.z * sW;
    C += (long)blockIdx.z * sC;
    __shared__ float As[16][68];
    __shared__ float Ws[16][68];
    int m0 = blockIdx.y * 64, n0 = blockIdx.x * 64;
    int tx = threadIdx.x, ty = threadIdx.y;
    int tid = ty * 16 + tx;
    float acc[4][4] = {};
    for (int kk = 0; kk < K; kk += 16) {
        #pragma unroll
        for (int s = 0; s < 4; s++) {
            int e = tid + s * 256;
            int mm = e >> 4, k = e & 15;
            float va = 0.f, vw = 0.f;
            if (m0 + mm < M && kk + k < K) va = A[(long)(m0 + mm) * K + kk + k];
            if (n0 + mm < N && kk + k < K) vw = W[(long)(n0 + mm) * K + kk + k];
            As[k][mm] = va;
            Ws[k][mm] = vw;
        }
        __syncthreads();
        #pragma unroll
        for (int k = 0; k < 16; k++) {
            float a[4], w[4];
            #pragma unroll
            for (int i = 0; i < 4; i++) a[i] = As[k][ty * 4 + i];
            #pragma unroll
            for (int j = 0; j < 4; j++) w[j] = Ws[k][tx * 4 + j];
            #pragma unroll
            for (int i = 0; i < 4; i++)
                #pragma unroll
                for (int j = 0; j < 4; j++) acc[i][j] += a[i] * w[j];
        }
        __syncthreads();
    }
    #pragma unroll
    for (int i = 0; i < 4; i++) {
        int m = m0 + ty * 4 + i;
        if (m >= M) continue;
        #pragma unroll
        for (int j = 0; j < 4; j++) {
            int n = n0 + tx * 4 + j;
            if (n >= N) continue;
            float v = acc[i][j];
            if (bias) v += bias[n];
            if (act == 1) v = tanhf(v);
            C[(long)m * N + n] = v;
        }
    }
}

// ---------------- persistent recurrence kernel ----------------
__global__ void __launch_bounds__(NTHR, 1) k_recurrence() {
    __shared__ float sh[2048];
    const int tid = blockIdx.x * NTHR + threadIdx.x;   // 0..32767

    // ===================== encoder =====================
    {
        const int hi  = tid >> 11;        // 0..15 = dir*8 + ks (block-uniform)
        const int ks  = hi & 7;
        const int dir = hi >> 3;
        const int n   = tid & (HG - 1);
        const int k0  = ks * (HH / KS);
        const float* WT = (dir ? g_WT_b : g_WT_f) + (long)k0 * HG + n;
        const float* hTsrc = g_heT + (long)dir * HH * BB + (long)k0 * BB;
        float* P = g_part_e + (long)hi * BB * HG + n;

        for (int t = 0; t < LK; t++) {
            for (int i = threadIdx.x; i < (HH / KS) * BB; i += NTHR)
                sh[i] = hTsrc[i];
            __syncthreads();
            float acc[16] = {};
            #pragma unroll 4
            for (int k = 0; k < HH / KS; k++) {
                float w = WT[(long)k * HG];
                const float4* h4 = (const float4*)(sh + k * BB);
                float4 h0 = h4[0], h1 = h4[1], h2 = h4[2], h3 = h4[3];
                acc[0]  += h0.x * w; acc[1]  += h0.y * w; acc[2]  += h0.z * w; acc[3]  += h0.w * w;
                acc[4]  += h1.x * w; acc[5]  += h1.y * w; acc[6]  += h1.z * w; acc[7]  += h1.w * w;
                acc[8]  += h2.x * w; acc[9]  += h2.y * w; acc[10] += h2.z * w; acc[11] += h2.w * w;
                acc[12] += h3.x * w; acc[13] += h3.y * w; acc[14] += h3.z * w; acc[15] += h3.w * w;
            }
            #pragma unroll
            for (int b = 0; b < 16; b++) P[(long)b * HG] = acc[b];
            gbar();

            if (tid < 2 * BB * HH) {
                int cdir = tid >> 13;
                int r = tid & (BB * HH - 1);
                int b = r >> 9, j = r & (HH - 1);
                int tt = cdir ? (LK - 1 - t) : t;
                const float* xg = cdir ? g_xg_b : g_xg_f;
                float gate[4];
                #pragma unroll
                for (int g = 0; g < 4; g++) {
                    int nn = g * HH + j;
                    float s = xg[((long)b * LK + tt) * HG + nn];
                    #pragma unroll
                    for (int q = 0; q < KS; q++)
                        s += g_part_e[(long)(cdir * KS + q) * BB * HG + (long)b * HG + nn];
                    gate[g] = s;
                }
                int si = cdir * BB * HH + b * HH + j;
                float c = sigf(gate[1]) * g_ce[si] + sigf(gate[0]) * tanhf(gate[2]);
                float h = sigf(gate[3]) * tanhf(c);
                g_ce[si] = c;
                g_heT[(long)cdir * HH * BB + (long)j * BB + b] = h;
                g_enc[((long)b * LK + tt) * H2 + cdir * HH + j] = h;
            }
            gbar();
        }
    }

    // ===================== decoder init =====================
    if (tid < BB * H2) {
        int b = tid >> 10, jj = tid & (H2 - 1);
        int dir = jj & 1, j = jj >> 1;
        g_hdT[(long)jj * BB + b] = g_heT[(long)dir * HH * BB + (long)j * BB + b];
        g_cd[tid] = g_ce[dir * BB * HH + b * HH + j];
    }
    gbar();

    // ===================== decoder =====================
    {
        const int ks = tid >> 12;         // 0..7, block-uniform
        const int n  = tid & (DG - 1);
        const int k0 = ks * (H2 / KS);
        const float* WT = g_WT_d + (long)k0 * DG + n;
        const float* hTsrc = g_hdT + (long)k0 * BB;
        float* P = g_part_d + (long)ks * BB * DG + n;

        for (int t = 0; t < LQ; t++) {
            for (int i = threadIdx.x; i < (H2 / KS) * BB; i += NTHR)
                sh[i] = hTsrc[i];
            __syncthreads();
            float acc[16] = {};
            #pragma unroll 4
            for (int k = 0; k < H2 / KS; k++) {
                float w = WT[(long)k * DG];
                const float4* h4 = (const float4*)(sh + k * BB);
                float4 h0 = h4[0], h1 = h4[1], h2 = h4[2], h3 = h4[3];
                acc[0]  += h0.x * w; acc[1]  += h0.y * w; acc[2]  += h0.z * w; acc[3]  += h0.w * w;
                acc[4]  += h1.x * w; acc[5]  += h1.y * w; acc[6]  += h1.z * w; acc[7]  += h1.w * w;
                acc[8]  += h2.x * w; acc[9]  += h2.y * w; acc[10] += h2.z * w; acc[11] += h2.w * w;
                acc[12] += h3.x * w; acc[13] += h3.y * w; acc[14] += h3.z * w; acc[15] += h3.w * w;
            }
            #pragma unroll
            for (int b = 0; b < 16; b++) P[(long)b * DG] = acc[b];
            gbar();

            if (tid < BB * H2) {
                int b = tid >> 10, j = tid & (H2 - 1);
                float gate[4];
                #pragma unroll
                for (int g = 0; g < 4; g++) {
                    int nn = g * H2 + j;
                    float s = g_xg_d[((long)b * LQ + t) * DG + nn];
                    #pragma unroll
                    for (int q = 0; q < KS; q++)
                        s += g_part_d[(long)q * BB * DG + (long)b * DG + nn];
                    gate[g] = s;
                }
                float c = sigf(gate[1]) * g_cd[tid] + sigf(gate[0]) * tanhf(gate[2]);
                float h = sigf(gate[3]) * tanhf(c);
                g_cd[tid] = c;
                g_hdT[(long)j * BB + b] = h;
                long base = (long)b * LQ + t;
                g_cat[base * (2 * H2) + H2 + j] = h;
                g_x1[base * H2 + j] = h;
            }
            gbar();
        }
    }
}

// ---------------- softmax over k with PAD mask ----------------
__global__ void k_softmax(const int* __restrict__ source) {
    int b = blockIdx.y, q = blockIdx.x;
    int k = threadIdx.x; // 64
    long off = ((long)b * LQ + q) * LK;
    float s = g_att[off + k];
    if (source[b * LK + k] == 0) s = -INFINITY;
    __shared__ float red[64];
    red[k] = s;
    __syncthreads();
    #pragma unroll
    for (int st = 32; st > 0; st >>= 1) {
        if (k < st) red[k] = fmaxf(red[k], red[k + st]);
        __syncthreads();
    }
    float mx = red[0];
    __syncthreads();
    float e = expf(s - mx);
    red[k] = e;
    __syncthreads();
    #pragma unroll
    for (int st = 32; st > 0; st >>= 1) {
        if (k < st) red[k] += red[k + st];
        __syncthreads();
    }
    g_att[off + k] = e / red[0];
}

// ---------------- ctx = A @ V into first half of concat buffer ----------------
__global__ void k_ctx() {
    int b = blockIdx.z;
    int q0 = blockIdx.y * 16;
    int c = blockIdx.x * 128 + threadIdx.x;
    __shared__ float As[16][64];
    for (int i = threadIdx.x; i < 16 * 64; i += 128)
        As[i / 64][i & 63] = g_att[((long)b * LQ + q0 + i / 64) * LK + (i & 63)];
    __syncthreads();
    float acc[16] = {};
    for (int k = 0; k < LK; k++) {
        float v = g_Vb[((long)b * LK + k) * H2 + c];
        #pragma unroll
        for (int q = 0; q < 16; q++) acc[q] += As[q][k] * v;
    }
    #pragma unroll
    for (int q = 0; q < 16; q++)
        g_cat[((long)b * LQ + q0 + q) * (2 * H2) + c] = acc[q];
}

// ---------------- host launch ----------------
extern "C" void kernel_launch(void* const* d_in, const int* in_sizes, int n_in,
                              void* d_out, int out_size) {
    const int*   source   = (const int*)  d_in[0];
    const int*   prev     = (const int*)  d_in[1];
    const float* emb      = (const float*)d_in[2];
    const float* ef_Wih   = (const float*)d_in[3];
    const float* ef_Whh   = (const float*)d_in[4];
    const float* ef_b     = (const float*)d_in[5];
    const float* eb_Wih   = (const float*)d_in[6];
    const float* eb_Whh   = (const float*)d_in[7];
    const float* eb_b     = (const float*)d_in[8];
    const float* d_Wih    = (const float*)d_in[9];
    const float* d_Whh    = (const float*)d_in[10];
    const float* d_b      = (const float*)d_in[11];
    const float* k_W      = (const float*)d_in[12];
    const float* k_b      = (const float*)d_in[13];
    const float* v_W      = (const float*)d_in[14];
    const float* v_b      = (const float*)d_in[15];
    const float* fc1_W    = (const float*)d_in[16];
    const float* fc1_b    = (const float*)d_in[17];
    const float* fc2_W    = (const float*)d_in[18];
    const float* fc2_b    = (const float*)d_in[19];
    float* out = (float*)d_out;

    float *p_xs_src, *p_xs_prev, *p_xg_f, *p_xg_b, *p_xg_d;
    float *p_WT_f, *p_WT_b, *p_WT_d, *p_enc, *p_K, *p_V, *p_att, *p_cat, *p_x1;
    cudaGetSymbolAddress((void**)&p_xs_src, g_xs_src);
    cudaGetSymbolAddress((void**)&p_xs_prev, g_xs_prev);
    cudaGetSymbolAddress((void**)&p_xg_f, g_xg_f);
    cudaGetSymbolAddress((void**)&p_xg_b, g_xg_b);
    cudaGetSymbolAddress((void**)&p_xg_d, g_xg_d);
    cudaGetSymbolAddress((void**)&p_WT_f, g_WT_f);
    cudaGetSymbolAddress((void**)&p_WT_b, g_WT_b);
    cudaGetSymbolAddress((void**)&p_WT_d, g_WT_d);
    cudaGetSymbolAddress((void**)&p_enc, g_enc);
    cudaGetSymbolAddress((void**)&p_K, g_Kb);
    cudaGetSymbolAddress((void**)&p_V, g_Vb);
    cudaGetSymbolAddress((void**)&p_att, g_att);
    cudaGetSymbolAddress((void**)&p_cat, g_cat);
    cudaGetSymbolAddress((void**)&p_x1, g_x1);

    // 0. zero encoder states
    k_zero_states<<<(2 * BB * HH + 255) / 256, 256>>>();

    // 1. embeddings
    k_embed<<<(BB * LK * DD + 255) / 256, 256>>>(source, emb, p_xs_src, BB * LK);
    k_embed<<<(BB * LQ * DD + 255) / 256, 256>>>(prev, emb, p_xs_prev, BB * LQ);

    // 2. transpose recurrent weights to k-major
    k_transpose<<<dim3((HH + 31) / 32, (HG + 31) / 32), dim3(32, 8)>>>(ef_Whh, p_WT_f, HG, HH);
    k_transpose<<<dim3((HH + 31) / 32, (HG + 31) / 32), dim3(32, 8)>>>(eb_Whh, p_WT_b, HG, HH);
    k_transpose<<<dim3((H2 + 31) / 32, (DG + 31) / 32), dim3(32, 8)>>>(d_Whh, p_WT_d, DG, H2);

    // 3. input pregates xg = xs @ Wih^T + b  (tf32 tensor-core GEMM)
    k_tgemm<<<dim3(HG / 128, (BB * LK) / 128), 256>>>(p_xs_src, ef_Wih, ef_b, p_xg_f,
        BB * LK, HG, DD, 0);
    k_tgemm<<<dim3(HG / 128, (BB * LK) / 128), 256>>>(p_xs_src, eb_Wih, eb_b, p_xg_b,
        BB * LK, HG, DD, 0);
    k_tgemm<<<dim3(DG / 128, (BB * LQ) / 128), 256>>>(p_xs_prev, d_Wih, d_b, p_xg_d,
        BB * LQ, DG, DD, 0);

    // 4+5. full recurrence in ONE persistent kernel
    k_recurrence<<<NBLK, NTHR>>>();

    // 6. K and V projections on enc_out  (tf32)
    k_tgemm<<<dim3(H2 / 128, (BB * LK) / 128), 256>>>(p_enc, k_W, k_b, p_K,
        BB * LK, H2, H2, 0);
    k_tgemm<<<dim3(H2 / 128, (BB * LK) / 128), 256>>>(p_enc, v_W, v_b, p_V,
        BB * LK, H2, H2, 0);

    // 7. scores M[b,q,k] = Q[b,q,:] · K[b,k,:]  (fp32, Q stored in g_x1)
    k_gemm<<<dim3(1, 1, BB), dim3(16, 16)>>>(p_x1, p_K, nullptr, p_att,
        LQ, LK, H2, (long)LQ * H2, (long)LK * H2, (long)LQ * LK, 0);

    // 8. masked softmax over k
    k_softmax<<<dim3(LQ, BB), 64>>>(source);

    // 9. ctx = A @ V into cat[:, :H2]
    k_ctx<<<dim3(H2 / 128, LQ / 16, BB), 128>>>();

    // 10. fc1 with tanh (tf32; overwrites Q temp storage in g_x1)
    k_tgemm<<<dim3(H2 / 128, (BB * LQ) / 128), 256>>>(p_cat, fc1_W, fc1_b, p_x1,
        BB * LQ, H2, 2 * H2, 1);

    // 11. fc2: out = x1 @ fc2_W^T + fc2_b  (tf32)
    k_tgemm<<<dim3((VV + 127) / 128, (BB * LQ) / 128), 256>>>(p_x1, fc2_W, fc2_b, out,
        BB * LQ, VV, H2, 0);
}

// round 13
// speedup vs baseline: 3.0878x; 1.2652x over previous
#include <cuda_runtime.h>
#include <math.h>
#include <stdint.h>

// ---------------- problem constants ----------------
#define BB   16      // batch
#define LK   64      // source length
#define LQ   64      // query length
#define DD   300     // embedding dim
#define HH   512     // encoder hidden
#define H2   1024    // 2*H (decoder hidden / enc_out channels)
#define HG   2048    // 4*H  encoder gates
#define DG   4096    // 8*H  decoder gates
#define VV   10000   // vocab
#define KS   8       // k-split (both enc and dec)

#define NBLK 128
#define NTHR 256

// ---------------- scratch (device globals; no allocation) ----------------
__device__ float g_xs_src[BB * LK * DD];
__device__ float g_xs_prev[BB * LQ * DD];
__device__ float g_xg_f[BB * LK * HG];
__device__ float g_xg_b[BB * LK * HG];
__device__ float g_xg_d[BB * LQ * DG];
__device__ float g_WT_f[HH * HG];
__device__ float g_WT_b[HH * HG];
__device__ float g_WT_d[H2 * DG];
__device__ float g_ce[2 * BB * HH];
__device__ float g_heT[2 * HH * BB];
__device__ float g_cd[BB * H2];
__device__ float g_hdT[H2 * BB];
__device__ float g_part_e[2 * KS * BB * HG];
__device__ float g_part_d[KS * BB * DG];
__device__ float g_enc[BB * LK * H2];
__device__ float g_Kb[BB * LK * H2];
__device__ float g_Vb[BB * LK * H2];
__device__ float g_att[BB * LQ * LK];
__device__ float g_cat[BB * LQ * 2 * H2];
__device__ float g_x1[BB * LQ * H2];

// grid barrier state (generation counter; self-resetting, replay-safe)
__device__ unsigned g_bar_cnt = 0;
__device__ unsigned g_bar_gen = 0;

__device__ __forceinline__ float sigf(float x) { return 1.f / (1.f + expf(-x)); }

__device__ __forceinline__ void gbar() {
    __syncthreads();
    if (threadIdx.x == 0) {
        volatile unsigned* genp = &g_bar_gen;
        __threadfence();
        unsigned g = *genp;
        if (atomicAdd(&g_bar_cnt, 1u) == NBLK - 1) {
            g_bar_cnt = 0;
            __threadfence();
            *genp = g + 1;
        } else {
            while (*genp == g) { }
            __threadfence();
        }
    }
    __syncthreads();
}

// ---------------- tf32 helpers (legacy mma.sync — compiles on compute_103) ----------
__device__ __forceinline__ unsigned f2tf32(float f) {
    unsigned r;
    asm("cvt.rna.tf32.f32 %0, %1;" : "=r"(r) : "f"(f));
    return r;
}

__device__ __forceinline__ void mma1688(float c[4], const unsigned a[4], const unsigned b[2]) {
    asm volatile(
        "mma.sync.aligned.m16n8k8.row.col.f32.tf32.tf32.f32 "
        "{%0,%1,%2,%3}, {%4,%5,%6,%7}, {%8,%9}, {%0,%1,%2,%3};"
        : "+f"(c[0]), "+f"(c[1]), "+f"(c[2]), "+f"(c[3])
        : "r"(a[0]), "r"(a[1]), "r"(a[2]), "r"(a[3]), "r"(b[0]), "r"(b[1]));
}

// ---------------- small utility kernels ----------------
__global__ void k_zero_states() {
    int i = blockIdx.x * blockDim.x + threadIdx.x;
    int n = 2 * BB * HH;
    if (i < n) { g_ce[i] = 0.f; g_heT[i] = 0.f; }
}

__global__ void k_embed(const int* __restrict__ idx, const float* __restrict__ emb,
                        float* __restrict__ out, int rows) {
    int i = blockIdx.x * blockDim.x + threadIdx.x;
    if (i < rows * DD) {
        int r = i / DD, d = i - r * DD;
        out[i] = emb[(long)idx[r] * DD + d];
    }
}

__global__ void k_transpose(const float* __restrict__ in, float* __restrict__ out,
                            int R, int C) {
    __shared__ float tile[32][33];
    int c0 = blockIdx.x * 32, r0 = blockIdx.y * 32;
    int c = c0 + threadIdx.x;
    #pragma unroll
    for (int i = 0; i < 32; i += 8) {
        int r = r0 + threadIdx.y + i;
        if (r < R && c < C) tile[threadIdx.y + i][threadIdx.x] = in[(long)r * C + c];
    }
    __syncthreads();
    int oc = r0 + threadIdx.x;
    #pragma unroll
    for (int i = 0; i < 32; i += 8) {
        int orr = c0 + threadIdx.y + i;
        if (orr < C && oc < R) out[(long)orr * R + oc] = tile[threadIdx.x][threadIdx.y + i];
    }
}

// ---------------- tf32 tensor-core GEMM with SW pipeline ----------------------------
// C[M,N] = A[M,K] @ W[N,K]^T (+bias)(+tanh)
// 128x128 tile, BK=32, 256 threads = 8 warps (2m x 4n), warp tile 64x32,
// mma.sync m16n8k8 tf32, fp32 accumulate. Global loads of chunk i+1 prefetched
// into registers while chunk i computes.
#define ASTRIDE 36
__global__ void __launch_bounds__(256, 1)
k_tgemm(const float* __restrict__ A, const float* __restrict__ W,
        const float* __restrict__ bias, float* __restrict__ C,
        int M, int N, int K, int act) {
    __shared__ unsigned As[128 * ASTRIDE];   // [m][k], padded
    __shared__ unsigned Ws[128 * ASTRIDE];   // [n][k], padded
    const int tid = threadIdx.x;
    const int warp = tid >> 5, lane = tid & 31;
    const int wm = warp >> 2, wn = warp & 3;   // 2 x 4 warp grid
    const int gid = lane >> 2, tig = lane & 3;
    const int m0 = blockIdx.y * 128, n0 = blockIdx.x * 128;
    const int rowA = m0 + (tid >> 3) ;   // helper below uses per-s rows
    (void)rowA;
    float acc[4][4][4] = {};   // [mi][ni][creg]

    const int nch = (K + 31) / 32;

    // per-thread staged registers for one chunk: 4 segments x float4 (A and W)
    float4 pa[4], pw[4];

    // ---- load chunk 0 into registers ----
    {
        const int kk = 0;
        #pragma unroll
        for (int s = 0; s < 4; s++) {
            int idx = tid + s * 256;
            int row = idx >> 3, c4 = (idx & 7) * 4;
            int kb = kk + c4;
            float4 va = make_float4(0.f, 0.f, 0.f, 0.f);
            if (m0 + row < M) {
                if (kb + 3 < K) va = *(const float4*)(A + (long)(m0 + row) * K + kb);
                else {
                    const float* p = A + (long)(m0 + row) * K;
                    va.x = (kb + 0 < K) ? p[kb + 0] : 0.f;
                    va.y = (kb + 1 < K) ? p[kb + 1] : 0.f;
                    va.z = (kb + 2 < K) ? p[kb + 2] : 0.f;
                    va.w = (kb + 3 < K) ? p[kb + 3] : 0.f;
                }
            }
            pa[s] = va;
            float4 vw = make_float4(0.f, 0.f, 0.f, 0.f);
            if (n0 + row < N) {
                if (kb + 3 < K) vw = *(const float4*)(W + (long)(n0 + row) * K + kb);
                else {
                    const float* p = W + (long)(n0 + row) * K;
                    vw.x = (kb + 0 < K) ? p[kb + 0] : 0.f;
                    vw.y = (kb + 1 < K) ? p[kb + 1] : 0.f;
                    vw.z = (kb + 2 < K) ? p[kb + 2] : 0.f;
                    vw.w = (kb + 3 < K) ? p[kb + 3] : 0.f;
                }
            }
            pw[s] = vw;
        }
    }

    for (int ch = 0; ch < nch; ch++) {
        // ---- commit staged registers to smem (tf32-rounded) ----
        __syncthreads();
        #pragma unroll
        for (int s = 0; s < 4; s++) {
            int idx = tid + s * 256;
            int row = idx >> 3, c4 = (idx & 7) * 4;
            uint4 ua;
            ua.x = f2tf32(pa[s].x); ua.y = f2tf32(pa[s].y);
            ua.z = f2tf32(pa[s].z); ua.w = f2tf32(pa[s].w);
            *(uint4*)(As + row * ASTRIDE + c4) = ua;
            uint4 uw;
            uw.x = f2tf32(pw[s].x); uw.y = f2tf32(pw[s].y);
            uw.z = f2tf32(pw[s].z); uw.w = f2tf32(pw[s].w);
            *(uint4*)(Ws + row * ASTRIDE + c4) = uw;
        }
        __syncthreads();

        // ---- prefetch chunk ch+1 into registers (overlaps with mma below) ----
        if (ch + 1 < nch) {
            const int kk = (ch + 1) * 32;
            #pragma unroll
            for (int s = 0; s < 4; s++) {
                int idx = tid + s * 256;
                int row = idx >> 3, c4 = (idx & 7) * 4;
                int kb = kk + c4;
                float4 va = make_float4(0.f, 0.f, 0.f, 0.f);
                if (m0 + row < M) {
                    if (kb + 3 < K) va = *(const float4*)(A + (long)(m0 + row) * K + kb);
                    else {
                        const float* p = A + (long)(m0 + row) * K;
                        va.x = (kb + 0 < K) ? p[kb + 0] : 0.f;
                        va.y = (kb + 1 < K) ? p[kb + 1] : 0.f;
                        va.z = (kb + 2 < K) ? p[kb + 2] : 0.f;
                        va.w = (kb + 3 < K) ? p[kb + 3] : 0.f;
                    }
                }
                pa[s] = va;
                float4 vw = make_float4(0.f, 0.f, 0.f, 0.f);
                if (n0 + row < N) {
                    if (kb + 3 < K) vw = *(const float4*)(W + (long)(n0 + row) * K + kb);
                    else {
                        const float* p = W + (long)(n0 + row) * K;
                        vw.x = (kb + 0 < K) ? p[kb + 0] : 0.f;
                        vw.y = (kb + 1 < K) ? p[kb + 1] : 0.f;
                        vw.z = (kb + 2 < K) ? p[kb + 2] : 0.f;
                        vw.w = (kb + 3 < K) ? p[kb + 3] : 0.f;
                    }
                }
                pw[s] = vw;
            }
        }

        // ---- compute: 4 x K=8 mma steps ----
        #pragma unroll
        for (int ki = 0; ki < 4; ki++) {
            const int k0 = ki * 8;
            unsigned a[4][4], b[4][2];
            #pragma unroll
            for (int mi = 0; mi < 4; mi++) {
                int mr = wm * 64 + mi * 16;
                a[mi][0] = As[(mr + gid)     * ASTRIDE + k0 + tig];
                a[mi][1] = As[(mr + gid + 8) * ASTRIDE + k0 + tig];
                a[mi][2] = As[(mr + gid)     * ASTRIDE + k0 + tig + 4];
                a[mi][3] = As[(mr + gid + 8) * ASTRIDE + k0 + tig + 4];
            }
            #pragma unroll
            for (int ni = 0; ni < 4; ni++) {
                int nr = wn * 32 + ni * 8;
                b[ni][0] = Ws[(nr + gid) * ASTRIDE + k0 + tig];
                b[ni][1] = Ws[(nr + gid) * ASTRIDE + k0 + tig + 4];
            }
            #pragma unroll
            for (int mi = 0; mi < 4; mi++)
                #pragma unroll
                for (int ni = 0; ni < 4; ni++)
                    mma1688(acc[mi][ni], a[mi], b[ni]);
        }
    }

    // epilogue
    #pragma unroll
    for (int mi = 0; mi < 4; mi++) {
        int m1 = m0 + wm * 64 + mi * 16 + gid;
        int m2 = m1 + 8;
        #pragma unroll
        for (int ni = 0; ni < 4; ni++) {
            int nc = n0 + wn * 32 + ni * 8 + 2 * tig;
            float b0 = 0.f, b1 = 0.f;
            if (bias) {
                if (nc < N)     b0 = bias[nc];
                if (nc + 1 < N) b1 = bias[nc + 1];
            }
            float v0 = acc[mi][ni][0] + b0;
            float v1 = acc[mi][ni][1] + b1;
            float v2 = acc[mi][ni][2] + b0;
            float v3 = acc[mi][ni][3] + b1;
            if (act == 1) { v0 = tanhf(v0); v1 = tanhf(v1); v2 = tanhf(v2); v3 = tanhf(v3); }
            if (m1 < M) {
                if (nc < N)     C[(long)m1 * N + nc]     = v0;
                if (nc + 1 < N) C[(long)m1 * N + nc + 1] = v1;
            }
            if (m2 < M) {
                if (nc < N)     C[(long)m2 * N + nc]     = v2;
                if (nc + 1 < N) C[(long)m2 * N + nc + 1] = v3;
            }
        }
    }
}

// ---------------- small batched GEMM for attention scores (fp32) ----------------
__global__ void k_gemm(const float* __restrict__ A, const float* __restrict__ W,
                       const float* __restrict__ bias, float* __restrict__ C,
                       int M, int N, int K, long sA, long sW, long sC, int act) {
    A += (long)blockIdx.z * sA;
    W += (long)blockIdx.z * sW;
    C += (long)blockIdx.z * sC;
    __shared__ float As[16][68];
    __shared__ float Ws[16][68];
    int m0 = blockIdx.y * 64, n0 = blockIdx.x * 64;
    int tx = threadIdx.x, ty = threadIdx.y;
    int tid = ty * 16 + tx;
    float acc[4][4] = {};
    for (int kk = 0; kk < K; kk += 16) {
        #pragma unroll
        for (int s = 0; s < 4; s++) {
            int e = tid + s * 256;
            int mm = e >> 4, k = e & 15;
            float va = 0.f, vw = 0.f;
            if (m0 + mm < M && kk + k < K) va = A[(long)(m0 + mm) * K + kk + k];
            if (n0 + mm < N && kk + k < K) vw = W[(long)(n0 + mm) * K + kk + k];
            As[k][mm] = va;
            Ws[k][mm] = vw;
        }
        __syncthreads();
        #pragma unroll
        for (int k = 0; k < 16; k++) {
            float a[4], w[4];
            #pragma unroll
            for (int i = 0; i < 4; i++) a[i] = As[k][ty * 4 + i];
            #pragma unroll
            for (int j = 0; j < 4; j++) w[j] = Ws[k][tx * 4 + j];
            #pragma unroll
            for (int i = 0; i < 4; i++)
                #pragma unroll
                for (int j = 0; j < 4; j++) acc[i][j] += a[i] * w[j];
        }
        __syncthreads();
    }
    #pragma unroll
    for (int i = 0; i < 4; i++) {
        int m = m0 + ty * 4 + i;
        if (m >= M) continue;
        #pragma unroll
        for (int j = 0; j < 4; j++) {
            int n = n0 + tx * 4 + j;
            if (n >= N) continue;
            float v = acc[i][j];
            if (bias) v += bias[n];
            if (act == 1) v = tanhf(v);
            C[(long)m * N + n] = v;
        }
    }
}

// ---------------- persistent recurrence kernel ----------------
__global__ void __launch_bounds__(NTHR, 1) k_recurrence() {
    __shared__ float sh[2048];
    const int tid = blockIdx.x * NTHR + threadIdx.x;

    // ===================== encoder =====================
    {
        const int hi  = tid >> 11;
        const int ks  = hi & 7;
        const int dir = hi >> 3;
        const int n   = tid & (HG - 1);
        const int k0  = ks * (HH / KS);
        const float* WT = (dir ? g_WT_b : g_WT_f) + (long)k0 * HG + n;
        const float* hTsrc = g_heT + (long)dir * HH * BB + (long)k0 * BB;
        float* P = g_part_e + (long)hi * BB * HG + n;

        for (int t = 0; t < LK; t++) {
            for (int i = threadIdx.x; i < (HH / KS) * BB; i += NTHR)
                sh[i] = hTsrc[i];
            __syncthreads();
            float acc[16] = {};
            #pragma unroll 4
            for (int k = 0; k < HH / KS; k++) {
                float w = WT[(long)k * HG];
                const float4* h4 = (const float4*)(sh + k * BB);
                float4 h0 = h4[0], h1 = h4[1], h2 = h4[2], h3 = h4[3];
                acc[0]  += h0.x * w; acc[1]  += h0.y * w; acc[2]  += h0.z * w; acc[3]  += h0.w * w;
                acc[4]  += h1.x * w; acc[5]  += h1.y * w; acc[6]  += h1.z * w; acc[7]  += h1.w * w;
                acc[8]  += h2.x * w; acc[9]  += h2.y * w; acc[10] += h2.z * w; acc[11] += h2.w * w;
                acc[12] += h3.x * w; acc[13] += h3.y * w; acc[14] += h3.z * w; acc[15] += h3.w * w;
            }
            #pragma unroll
            for (int b = 0; b < 16; b++) P[(long)b * HG] = acc[b];
            gbar();

            if (tid < 2 * BB * HH) {
                int cdir = tid >> 13;
                int r = tid & (BB * HH - 1);
                int b = r >> 9, j = r & (HH - 1);
                int tt = cdir ? (LK - 1 - t) : t;
                const float* xg = cdir ? g_xg_b : g_xg_f;
                float gate[4];
                #pragma unroll
                for (int g = 0; g < 4; g++) {
                    int nn = g * HH + j;
                    float s = xg[((long)b * LK + tt) * HG + nn];
                    #pragma unroll
                    for (int q = 0; q < KS; q++)
                        s += g_part_e[(long)(cdir * KS + q) * BB * HG + (long)b * HG + nn];
                    gate[g] = s;
                }
                int si = cdir * BB * HH + b * HH + j;
                float c = sigf(gate[1]) * g_ce[si] + sigf(gate[0]) * tanhf(gate[2]);
                float h = sigf(gate[3]) * tanhf(c);
                g_ce[si] = c;
                g_heT[(long)cdir * HH * BB + (long)j * BB + b] = h;
                g_enc[((long)b * LK + tt) * H2 + cdir * HH + j] = h;
            }
            gbar();
        }
    }

    // ===================== decoder init =====================
    if (tid < BB * H2) {
        int b = tid >> 10, jj = tid & (H2 - 1);
        int dir = jj & 1, j = jj >> 1;
        g_hdT[(long)jj * BB + b] = g_heT[(long)dir * HH * BB + (long)j * BB + b];
        g_cd[tid] = g_ce[dir * BB * HH + b * HH + j];
    }
    gbar();

    // ===================== decoder =====================
    {
        const int ks = tid >> 12;
        const int n  = tid & (DG - 1);
        const int k0 = ks * (H2 / KS);
        const float* WT = g_WT_d + (long)k0 * DG + n;
        const float* hTsrc = g_hdT + (long)k0 * BB;
        float* P = g_part_d + (long)ks * BB * DG + n;

        for (int t = 0; t < LQ; t++) {
            for (int i = threadIdx.x; i < (H2 / KS) * BB; i += NTHR)
                sh[i] = hTsrc[i];
            __syncthreads();
            float acc[16] = {};
            #pragma unroll 4
            for (int k = 0; k < H2 / KS; k++) {
                float w = WT[(long)k * DG];
                const float4* h4 = (const float4*)(sh + k * BB);
                float4 h0 = h4[0], h1 = h4[1], h2 = h4[2], h3 = h4[3];
                acc[0]  += h0.x * w; acc[1]  += h0.y * w; acc[2]  += h0.z * w; acc[3]  += h0.w * w;
                acc[4]  += h1.x * w; acc[5]  += h1.y * w; acc[6]  += h1.z * w; acc[7]  += h1.w * w;
                acc[8]  += h2.x * w; acc[9]  += h2.y * w; acc[10] += h2.z * w; acc[11] += h2.w * w;
                acc[12] += h3.x * w; acc[13] += h3.y * w; acc[14] += h3.z * w; acc[15] += h3.w * w;
            }
            #pragma unroll
            for (int b = 0; b < 16; b++) P[(long)b * DG] = acc[b];
            gbar();

            if (tid < BB * H2) {
                int b = tid >> 10, j = tid & (H2 - 1);
                float gate[4];
                #pragma unroll
                for (int g = 0; g < 4; g++) {
                    int nn = g * H2 + j;
                    float s = g_xg_d[((long)b * LQ + t) * DG + nn];
                    #pragma unroll
                    for (int q = 0; q < KS; q++)
                        s += g_part_d[(long)q * BB * DG + (long)b * DG + nn];
                    gate[g] = s;
                }
                float c = sigf(gate[1]) * g_cd[tid] + sigf(gate[0]) * tanhf(gate[2]);
                float h = sigf(gate[3]) * tanhf(c);
                g_cd[tid] = c;
                g_hdT[(long)j * BB + b] = h;
                long base = (long)b * LQ + t;
                g_cat[base * (2 * H2) + H2 + j] = h;
                g_x1[base * H2 + j] = h;
            }
            gbar();
        }
    }
}

// ---------------- softmax over k with PAD mask ----------------
__global__ void k_softmax(const int* __restrict__ source) {
    int b = blockIdx.y, q = blockIdx.x;
    int k = threadIdx.x;
    long off = ((long)b * LQ + q) * LK;
    float s = g_att[off + k];
    if (source[b * LK + k] == 0) s = -INFINITY;
    __shared__ float red[64];
    red[k] = s;
    __syncthreads();
    #pragma unroll
    for (int st = 32; st > 0; st >>= 1) {
        if (k < st) red[k] = fmaxf(red[k], red[k + st]);
        __syncthreads();
    }
    float mx = red[0];
    __syncthreads();
    float e = expf(s - mx);
    red[k] = e;
    __syncthreads();
    #pragma unroll
    for (int st = 32; st > 0; st >>= 1) {
        if (k < st) red[k] += red[k + st];
        __syncthreads();
    }
    g_att[off + k] = e / red[0];
}

// ---------------- ctx = A @ V into first half of concat buffer ----------------
__global__ void k_ctx() {
    int b = blockIdx.z;
    int q0 = blockIdx.y * 16;
    int c = blockIdx.x * 128 + threadIdx.x;
    __shared__ float As[16][64];
    for (int i = threadIdx.x; i < 16 * 64; i += 128)
        As[i / 64][i & 63] = g_att[((long)b * LQ + q0 + i / 64) * LK + (i & 63)];
    __syncthreads();
    float acc[16] = {};
    for (int k = 0; k < LK; k++) {
        float v = g_Vb[((long)b * LK + k) * H2 + c];
        #pragma unroll
        for (int q = 0; q < 16; q++) acc[q] += As[q][k] * v;
    }
    #pragma unroll
    for (int q = 0; q < 16; q++)
        g_cat[((long)b * LQ + q0 + q) * (2 * H2) + c] = acc[q];
}

// ---------------- host launch ----------------
extern "C" void kernel_launch(void* const* d_in, const int* in_sizes, int n_in,
                              void* d_out, int out_size) {
    const int*   source   = (const int*)  d_in[0];
    const int*   prev     = (const int*)  d_in[1];
    const float* emb      = (const float*)d_in[2];
    const float* ef_Wih   = (const float*)d_in[3];
    const float* ef_Whh   = (const float*)d_in[4];
    const float* ef_b     = (const float*)d_in[5];
    const float* eb_Wih   = (const float*)d_in[6];
    const float* eb_Whh   = (const float*)d_in[7];
    const float* eb_b     = (const float*)d_in[8];
    const float* d_Wih    = (const float*)d_in[9];
    const float* d_Whh    = (const float*)d_in[10];
    const float* d_b      = (const float*)d_in[11];
    const float* k_W      = (const float*)d_in[12];
    const float* k_b      = (const float*)d_in[13];
    const float* v_W      = (const float*)d_in[14];
    const float* v_b      = (const float*)d_in[15];
    const float* fc1_W    = (const float*)d_in[16];
    const float* fc1_b    = (const float*)d_in[17];
    const float* fc2_W    = (const float*)d_in[18];
    const float* fc2_b    = (const float*)d_in[19];
    float* out = (float*)d_out;

    float *p_xs_src, *p_xs_prev, *p_xg_f, *p_xg_b, *p_xg_d;
    float *p_WT_f, *p_WT_b, *p_WT_d, *p_enc, *p_K, *p_V, *p_att, *p_cat, *p_x1;
    cudaGetSymbolAddress((void**)&p_xs_src, g_xs_src);
    cudaGetSymbolAddress((void**)&p_xs_prev, g_xs_prev);
    cudaGetSymbolAddress((void**)&p_xg_f, g_xg_f);
    cudaGetSymbolAddress((void**)&p_xg_b, g_xg_b);
    cudaGetSymbolAddress((void**)&p_xg_d, g_xg_d);
    cudaGetSymbolAddress((void**)&p_WT_f, g_WT_f);
    cudaGetSymbolAddress((void**)&p_WT_b, g_WT_b);
    cudaGetSymbolAddress((void**)&p_WT_d, g_WT_d);
    cudaGetSymbolAddress((void**)&p_enc, g_enc);
    cudaGetSymbolAddress((void**)&p_K, g_Kb);
    cudaGetSymbolAddress((void**)&p_V, g_Vb);
    cudaGetSymbolAddress((void**)&p_att, g_att);
    cudaGetSymbolAddress((void**)&p_cat, g_cat);
    cudaGetSymbolAddress((void**)&p_x1, g_x1);

    // 1-3. zero + embeddings
    k_zero_states<<<(2 * BB * HH + 255) / 256, 256>>>();
    k_embed<<<(BB * LK * DD + 255) / 256, 256>>>(source, emb, p_xs_src, BB * LK);
    k_embed<<<(BB * LQ * DD + 255) / 256, 256>>>(prev, emb, p_xs_prev, BB * LQ);

    // 4-6. input pregates (tf32 mma) — launch #6 (xg_d) is what ncu -s 5 -c 1 profiles
    k_tgemm<<<dim3(HG / 128, (BB * LK) / 128), 256>>>(p_xs_src, ef_Wih, ef_b, p_xg_f,
        BB * LK, HG, DD, 0);
    k_tgemm<<<dim3(HG / 128, (BB * LK) / 128), 256>>>(p_xs_src, eb_Wih, eb_b, p_xg_b,
        BB * LK, HG, DD, 0);
    k_tgemm<<<dim3(DG / 128, (BB * LQ) / 128), 256>>>(p_xs_prev, d_Wih, d_b, p_xg_d,
        BB * LQ, DG, DD, 0);

    // 7-9. transpose recurrent weights to k-major
    k_transpose<<<dim3((HH + 31) / 32, (HG + 31) / 32), dim3(32, 8)>>>(ef_Whh, p_WT_f, HG, HH);
    k_transpose<<<dim3((HH + 31) / 32, (HG + 31) / 32), dim3(32, 8)>>>(eb_Whh, p_WT_b, HG, HH);
    k_transpose<<<dim3((H2 + 31) / 32, (DG + 31) / 32), dim3(32, 8)>>>(d_Whh, p_WT_d, DG, H2);

    // 10. full recurrence in ONE persistent kernel
    k_recurrence<<<NBLK, NTHR>>>();

    // 11-12. K and V projections
    k_tgemm<<<dim3(H2 / 128, (BB * LK) / 128), 256>>>(p_enc, k_W, k_b, p_K,
        BB * LK, H2, H2, 0);
    k_tgemm<<<dim3(H2 / 128, (BB * LK) / 128), 256>>>(p_enc, v_W, v_b, p_V,
        BB * LK, H2, H2, 0);

    // 13. scores (fp32, Q stored in g_x1)
    k_gemm<<<dim3(1, 1, BB), dim3(16, 16)>>>(p_x1, p_K, nullptr, p_att,
        LQ, LK, H2, (long)LQ * H2, (long)LK * H2, (long)LQ * LK, 0);

    // 14. masked softmax
    k_softmax<<<dim3(LQ, BB), 64>>>(source);

    // 15. ctx = A @ V
    k_ctx<<<dim3(H2 / 128, LQ / 16, BB), 128>>>();

    // 16. fc1 with tanh (overwrites Q temp storage)
    k_tgemm<<<dim3(H2 / 128, (BB * LQ) / 128), 256>>>(p_cat, fc1_W, fc1_b, p_x1,
        BB * LQ, H2, 2 * H2, 1);

    // 17. fc2
    k_tgemm<<<dim3((VV + 127) / 128, (BB * LQ) / 128), 256>>>(p_x1, fc2_W, fc2_b, out,
        BB * LQ, VV, H2, 0);
}